// round 8
// baseline (speedup 1.0000x reference)
#include <cuda_runtime.h>
#include <cuda_bf16.h>
#include <math.h>
#include <stdint.h>

#define Bn   16384
#define HIDn 4096
#define HDn  256
#define YSW  132   // ys plane row stride (words)
#define APh0 17    // A plane row stride, h-GEMMs (16 words + 1 pad)

// ---------------- scratch ----------------
__device__ float g_H0[Bn * HDn];
__device__ float g_X[Bn * 16];
// pair-packed split-bf16 weight planes: word(chunk,n,k2) = {W[16c+2k2][n], W[16c+2k2+1][n]}
// index = chunk*(N*8) + n*8 + k2
__device__ uint32_t g_W0h[256 * 2048], g_W0l[256 * 2048];  // W0[:4096,:256]
__device__ uint32_t g_Wrh[48 * 2048],  g_Wrl[48 * 2048];   // Wr 3x256x256 (gc = l*16+chunk)
__device__ uint32_t g_G1h[256 * 512],  g_G1l[256 * 512];   // gW1 4096x64

// ---------------- helpers ----------------
__device__ __forceinline__ float gelu_f(float x) {
    return 0.5f * x * (1.0f + erff(x * 0.70710678118654752f));
}
__device__ __forceinline__ float sigmoid_f(float x) {
    return 1.0f / (1.0f + expf(-x));
}
__device__ __forceinline__ uint32_t packsplit(float v0, float v1, uint32_t& lo) {
    __nv_bfloat16 h0 = __float2bfloat16_rn(v0), h1 = __float2bfloat16_rn(v1);
    __nv_bfloat162 L = __floats2bfloat162_rn(v0 - __bfloat162float(h0),
                                             v1 - __bfloat162float(h1));
    lo = *(uint32_t*)&L;
    __nv_bfloat162 H = __halves2bfloat162(h0, h1);
    return *(uint32_t*)&H;
}
__device__ __forceinline__ float2 unpk(uint32_t w) {
    __nv_bfloat162 t = *(__nv_bfloat162*)&w;
    return make_float2(__bfloat162float(t.x), __bfloat162float(t.y));
}
__device__ __forceinline__ void mma_bf16(float* c, uint32_t a0, uint32_t a1,
                                         uint32_t a2, uint32_t a3,
                                         uint32_t b0, uint32_t b1) {
    asm volatile(
        "mma.sync.aligned.m16n8k16.row.col.f32.bf16.bf16.f32 "
        "{%0,%1,%2,%3}, {%4,%5,%6,%7}, {%8,%9}, {%0,%1,%2,%3};"
        : "+f"(c[0]), "+f"(c[1]), "+f"(c[2]), "+f"(c[3])
        : "r"(a0), "r"(a1), "r"(a2), "r"(a3), "r"(b0), "r"(b1));
}
__device__ __forceinline__ void mma3(float* c, const uint32_t* ah, const uint32_t* al,
                                     uint32_t bh0, uint32_t bh1,
                                     uint32_t bl0, uint32_t bl1) {
    mma_bf16(c, ah[0], ah[1], ah[2], ah[3], bh0, bh1);
    mma_bf16(c, ah[0], ah[1], ah[2], ah[3], bl0, bl1);
    mma_bf16(c, al[0], al[1], al[2], al[3], bh0, bh1);
}
__device__ __forceinline__ uint32_t sm_u32(const void* p) {
    return (uint32_t)__cvta_generic_to_shared(p);
}
#define CPA16(d, s) asm volatile("cp.async.cg.shared.global [%0],[%1],16;" ::"r"(d), "l"(s))
#define CPCOMMIT    asm volatile("cp.async.commit_group;")
#define CPWAIT0     asm volatile("cp.async.wait_group 0;" ::: "memory")

__device__ __forceinline__ void exp_se3_dev(const float* xi, float* X) {
    float wx = xi[0], wy = xi[1], wz = xi[2];
    float vx = xi[3], vy = xi[4], vz = xi[5];
    float th2 = wx * wx + wy * wy + wz * wz + 1e-20f;
    float th  = sqrtf(th2);
    bool small = th < 1e-3f;
    float ths = small ? 1.0f : th;
    float s = sinf(ths), c = cosf(ths);
    float A  = small ? (1.0f - th2 / 6.0f)          : (s / ths);
    float Bc = small ? (0.5f - th2 / 24.0f)         : ((1.0f - c) / (ths * ths));
    float Cc = small ? (1.0f / 6.0f - th2 / 120.0f) : ((ths - s) / (ths * ths * ths));
    float wx2 = wx * wx, wy2 = wy * wy, wz2 = wz * wz;
    float xy = wx * wy, xz = wx * wz, yz = wy * wz;
    float R00 = 1.0f - Bc * (wy2 + wz2), R01 = -A * wz + Bc * xy, R02 =  A * wy + Bc * xz;
    float R10 =  A * wz + Bc * xy, R11 = 1.0f - Bc * (wx2 + wz2), R12 = -A * wx + Bc * yz;
    float R20 = -A * wy + Bc * xz, R21 =  A * wx + Bc * yz, R22 = 1.0f - Bc * (wx2 + wy2);
    float V00 = 1.0f - Cc * (wy2 + wz2), V01 = -Bc * wz + Cc * xy, V02 =  Bc * wy + Cc * xz;
    float V10 =  Bc * wz + Cc * xy, V11 = 1.0f - Cc * (wx2 + wz2), V12 = -Bc * wx + Cc * yz;
    float V20 = -Bc * wy + Cc * xz, V21 =  Bc * wx + Cc * yz, V22 = 1.0f - Cc * (wx2 + wy2);
    X[0] = R00; X[1] = R01; X[2]  = R02; X[3]  = V00 * vx + V01 * vy + V02 * vz;
    X[4] = R10; X[5] = R11; X[6]  = R12; X[7]  = V10 * vx + V11 * vy + V12 * vz;
    X[8] = R20; X[9] = R21; X[10] = R22; X[11] = V20 * vx + V21 * vy + V22 * vz;
    X[12] = 0.0f; X[13] = 0.0f; X[14] = 0.0f; X[15] = 1.0f;
}

__device__ __forceinline__ void log_se3_dev(const float* X, float* xi) {
    float R00 = X[0], R01 = X[1], R02 = X[2],  px = X[3];
    float R10 = X[4], R11 = X[5], R12 = X[6],  py = X[7];
    float R20 = X[8], R21 = X[9], R22 = X[10], pz = X[11];
    float tr = R00 + R11 + R22;
    float cc = fminf(fmaxf((tr - 1.0f) * 0.5f, -1.0f + 1e-7f), 1.0f - 1e-7f);
    float th = acosf(cc);
    bool small = th < 1e-3f;
    float ths = small ? 1.0f : th;
    float sn = sinf(ths), csn = cosf(ths);
    float fac = small ? (0.5f + th * th / 12.0f) : (ths / (2.0f * sn));
    float wx = fac * (R21 - R12);
    float wy = fac * (R02 - R20);
    float wz = fac * (R10 - R01);
    float D = small ? (1.0f / 12.0f)
                    : ((1.0f - ths * sn / (2.0f * (1.0f - csn))) / (ths * ths));
    float wx2 = wx * wx, wy2 = wy * wy, wz2 = wz * wz;
    float xy = wx * wy, xz = wx * wz, yz = wy * wz;
    float V00 = 1.0f - D * (wy2 + wz2), V01 =  0.5f * wz + D * xy, V02 = -0.5f * wy + D * xz;
    float V10 = -0.5f * wz + D * xy, V11 = 1.0f - D * (wx2 + wz2), V12 =  0.5f * wx + D * yz;
    float V20 =  0.5f * wy + D * xz, V21 = -0.5f * wx + D * yz, V22 = 1.0f - D * (wx2 + wy2);
    xi[0] = wx; xi[1] = wy; xi[2] = wz;
    xi[3] = V00 * px + V01 * py + V02 * pz;
    xi[4] = V10 * px + V11 * py + V12 * pz;
    xi[5] = V20 * px + V21 * py + V22 * pz;
}

// ---------------- weight prep ----------------
__global__ void prep_w0(const float* __restrict__ W0) {
    int w = blockIdx.x * 256 + threadIdx.x;   // 524288
    int k2 = w & 7, n = (w >> 3) & 255, ch = w >> 11;
    int k = ch * 16 + 2 * k2;
    uint32_t lo, hi = packsplit(W0[(size_t)k * HDn + n], W0[(size_t)(k + 1) * HDn + n], lo);
    g_W0h[w] = hi; g_W0l[w] = lo;
}
__global__ void prep_wr(const float* __restrict__ Wr) {
    int w = blockIdx.x * 256 + threadIdx.x;   // 98304
    int k2 = w & 7, n = (w >> 3) & 255, gc = w >> 11;
    int l = gc >> 4, ch = gc & 15;
    int k = ch * 16 + 2 * k2;
    const float* s = Wr + (size_t)l * HDn * HDn + (size_t)k * HDn + n;
    uint32_t lo, hi = packsplit(s[0], s[HDn], lo);
    g_Wrh[w] = hi; g_Wrl[w] = lo;
}
__global__ void prep_g1(const float* __restrict__ gW1) {
    int w = blockIdx.x * 256 + threadIdx.x;   // 131072
    int k2 = w & 7, n = (w >> 3) & 63, ch = w >> 9;
    int k = ch * 16 + 2 * k2;
    uint32_t lo, hi = packsplit(gW1[(size_t)k * 64 + n], gW1[(size_t)(k + 1) * 64 + n], lo);
    g_G1h[w] = hi; g_G1l[w] = lo;
}

// ---------------- init ----------------
__global__ void init_kernel(const float* __restrict__ xi0) {
    int r = blockIdx.x * blockDim.x + threadIdx.x;
    if (r >= Bn) return;
    float xi[6];
#pragma unroll
    for (int j = 0; j < 6; j++) xi[j] = 0.1f * xi0[r * 6 + j];
    float X[16];
    exp_se3_dev(xi, X);
#pragma unroll
    for (int j = 0; j < 16; j++) g_X[(size_t)r * 16 + j] = X[j];
}

// ---------------- H0 = h @ W0[:4096] + b0, split-bf16 ----------------
// block 128M x 256N, 512 thr (16 warps, 4Mx4N, warp 32x64), k-tile 32 (2 k16 chunks)
__global__ void __launch_bounds__(512, 1) gemm_h0_kernel(
    const float* __restrict__ h, const float* __restrict__ bias0) {
    extern __shared__ uint32_t dsm[];
    uint32_t* Ah = dsm;                 // 128*17
    uint32_t* Al = Ah + 128 * APh0;     // 128*17
    uint32_t* Bb = Al + 128 * APh0;     // 2 buf * 8192
    int brow = blockIdx.x * 128;
    int tid = threadIdx.x, wid = tid >> 5, lane = tid & 31;
    int g = lane >> 2, t = lane & 3;
    int warp_m = (wid >> 2) * 32, warp_n = (wid & 3) * 64;
    int ar = tid >> 2, aq = tid & 3;

    float acc[2][8][4];
#pragma unroll
    for (int mf = 0; mf < 2; mf++)
#pragma unroll
        for (int nf = 0; nf < 8; nf++)
#pragma unroll
            for (int q = 0; q < 4; q++) acc[mf][nf][q] = 0.0f;

    // prologue: B tile0 + A regs tile0
#pragma unroll
    for (int q = 0; q < 4; q++) {
        int f = (tid + q * 512) * 4;
        int cc = f >> 12, p = (f >> 11) & 1, off = f & 2047;
        const uint32_t* src = (p ? g_W0l : g_W0h) + (size_t)cc * 2048 + off;
        CPA16(sm_u32(&Bb[f]), src);
    }
    CPCOMMIT;
    float4 a4[2];
    {
        const float* s = h + (size_t)(brow + ar) * HIDn + aq * 8;
        a4[0] = *(const float4*)s; a4[1] = *(const float4*)(s + 4);
    }

    for (int tl = 0; tl < 128; tl++) {
        CPWAIT0;
        __syncthreads();
        // store A (split) from prefetched regs
        {
            uint32_t* ph = Ah + ar * APh0 + aq * 4;
            uint32_t* pl = Al + ar * APh0 + aq * 4;
            uint32_t lo;
            ph[0] = packsplit(a4[0].x, a4[0].y, lo); pl[0] = lo;
            ph[1] = packsplit(a4[0].z, a4[0].w, lo); pl[1] = lo;
            ph[2] = packsplit(a4[1].x, a4[1].y, lo); pl[2] = lo;
            ph[3] = packsplit(a4[1].z, a4[1].w, lo); pl[3] = lo;
        }
        if (tl + 1 < 128) {
            int c0 = (tl + 1) * 2, nb = (tl + 1) & 1;
#pragma unroll
            for (int q = 0; q < 4; q++) {
                int f = (tid + q * 512) * 4;
                int cc = f >> 12, p = (f >> 11) & 1, off = f & 2047;
                const uint32_t* src = (p ? g_W0l : g_W0h) + (size_t)(c0 + cc) * 2048 + off;
                CPA16(sm_u32(&Bb[nb * 8192 + f]), src);
            }
            CPCOMMIT;
        }
        __syncthreads();
        if (tl + 1 < 128) {
            const float* s = h + (size_t)(brow + ar) * HIDn + (tl + 1) * 32 + aq * 8;
            a4[0] = *(const float4*)s; a4[1] = *(const float4*)(s + 4);
        }
        const uint32_t* Bc = Bb + (tl & 1) * 8192;
#pragma unroll
        for (int cc = 0; cc < 2; cc++) {
            uint32_t ah[2][4], al[2][4];
#pragma unroll
            for (int mf = 0; mf < 2; mf++) {
                int b0 = (warp_m + mf * 16 + g) * APh0 + cc * 8;
                ah[mf][0] = Ah[b0 + t];     ah[mf][1] = Ah[b0 + 8 * APh0 + t];
                ah[mf][2] = Ah[b0 + t + 4]; ah[mf][3] = Ah[b0 + 8 * APh0 + t + 4];
                al[mf][0] = Al[b0 + t];     al[mf][1] = Al[b0 + 8 * APh0 + t];
                al[mf][2] = Al[b0 + t + 4]; al[mf][3] = Al[b0 + 8 * APh0 + t + 4];
            }
            const uint32_t* Bh = Bc + cc * 4096;
#pragma unroll
            for (int nf = 0; nf < 8; nf++) {
                int nn = (warp_n + nf * 8 + g) * 8;
                uint32_t bh0 = Bh[nn + t], bh1 = Bh[nn + t + 4];
                uint32_t bl0 = Bh[2048 + nn + t], bl1 = Bh[2048 + nn + t + 4];
                mma3(acc[0][nf], ah[0], al[0], bh0, bh1, bl0, bl1);
                mma3(acc[1][nf], ah[1], al[1], bh0, bh1, bl0, bl1);
            }
        }
    }
#pragma unroll
    for (int mf = 0; mf < 2; mf++) {
        int r0 = brow + warp_m + mf * 16 + g;
#pragma unroll
        for (int nf = 0; nf < 8; nf++) {
            int c0 = warp_n + nf * 8 + 2 * t;
            float2 bb = *(const float2*)&bias0[c0];
            *(float2*)&g_H0[(size_t)r0 * HDn + c0] =
                make_float2(acc[mf][nf][0] + bb.x, acc[mf][nf][1] + bb.y);
            *(float2*)&g_H0[(size_t)(r0 + 8) * HDn + c0] =
                make_float2(acc[mf][nf][2] + bb.x, acc[mf][nf][3] + bb.y);
        }
    }
}

// ---------------- gripper, split-bf16 ----------------
// block 128M x 64N, 256 thr (8 warps, 4Mx2N, warp 32x32)
__global__ void __launch_bounds__(256, 1) gripper_kernel(
    const float* __restrict__ h, const float* __restrict__ gb1,
    const float* __restrict__ gW2, const float* __restrict__ gb2,
    float* __restrict__ out) {
    __shared__ __align__(16) uint32_t Ah[128 * APh0], Al[128 * APh0];
    __shared__ __align__(16) uint32_t Bb[2 * 2048];
    __shared__ float sred[128][2];
    int brow = blockIdx.x * 128;
    int tid = threadIdx.x, wid = tid >> 5, lane = tid & 31;
    int g = lane >> 2, t = lane & 3;
    int warp_m = (wid >> 1) * 32, warp_n = (wid & 1) * 32;
    int ar = tid >> 1, aq = tid & 1;

    float acc[2][4][4];
#pragma unroll
    for (int mf = 0; mf < 2; mf++)
#pragma unroll
        for (int nf = 0; nf < 4; nf++)
#pragma unroll
            for (int q = 0; q < 4; q++) acc[mf][nf][q] = 0.0f;

#pragma unroll
    for (int q = 0; q < 2; q++) {
        int f = (tid + q * 256) * 4;
        int cc = f >> 10, p = (f >> 9) & 1, off = f & 511;
        const uint32_t* src = (p ? g_G1l : g_G1h) + (size_t)cc * 512 + off;
        CPA16(sm_u32(&Bb[f]), src);
    }
    CPCOMMIT;
    float4 a4[4];
    {
        const float* s = h + (size_t)(brow + ar) * HIDn + aq * 16;
#pragma unroll
        for (int i = 0; i < 4; i++) a4[i] = *(const float4*)(s + i * 4);
    }

    for (int tl = 0; tl < 128; tl++) {
        CPWAIT0;
        __syncthreads();
        {
            uint32_t* ph = Ah + ar * APh0 + aq * 8;
            uint32_t* pl = Al + ar * APh0 + aq * 8;
            uint32_t lo;
#pragma unroll
            for (int i = 0; i < 4; i++) {
                ph[2 * i]     = packsplit(a4[i].x, a4[i].y, lo); pl[2 * i]     = lo;
                ph[2 * i + 1] = packsplit(a4[i].z, a4[i].w, lo); pl[2 * i + 1] = lo;
            }
        }
        if (tl + 1 < 128) {
            int c0 = (tl + 1) * 2, nb = (tl + 1) & 1;
#pragma unroll
            for (int q = 0; q < 2; q++) {
                int f = (tid + q * 256) * 4;
                int cc = f >> 10, p = (f >> 9) & 1, off = f & 511;
                const uint32_t* src = (p ? g_G1l : g_G1h) + (size_t)(c0 + cc) * 512 + off;
                CPA16(sm_u32(&Bb[nb * 2048 + f]), src);
            }
            CPCOMMIT;
        }
        __syncthreads();
        if (tl + 1 < 128) {
            const float* s = h + (size_t)(brow + ar) * HIDn + (tl + 1) * 32 + aq * 16;
#pragma unroll
            for (int i = 0; i < 4; i++) a4[i] = *(const float4*)(s + i * 4);
        }
        const uint32_t* Bc = Bb + (tl & 1) * 2048;
#pragma unroll
        for (int cc = 0; cc < 2; cc++) {
            uint32_t ah[2][4], al[2][4];
#pragma unroll
            for (int mf = 0; mf < 2; mf++) {
                int b0 = (warp_m + mf * 16 + g) * APh0 + cc * 8;
                ah[mf][0] = Ah[b0 + t];     ah[mf][1] = Ah[b0 + 8 * APh0 + t];
                ah[mf][2] = Ah[b0 + t + 4]; ah[mf][3] = Ah[b0 + 8 * APh0 + t + 4];
                al[mf][0] = Al[b0 + t];     al[mf][1] = Al[b0 + 8 * APh0 + t];
                al[mf][2] = Al[b0 + t + 4]; al[mf][3] = Al[b0 + 8 * APh0 + t + 4];
            }
            const uint32_t* Bh = Bc + cc * 1024;
#pragma unroll
            for (int nf = 0; nf < 4; nf++) {
                int nn = (warp_n + nf * 8 + g) * 8;
                uint32_t bh0 = Bh[nn + t], bh1 = Bh[nn + t + 4];
                uint32_t bl0 = Bh[512 + nn + t], bl1 = Bh[512 + nn + t + 4];
                mma3(acc[0][nf], ah[0], al[0], bh0, bh1, bl0, bl1);
                mma3(acc[1][nf], ah[1], al[1], bh0, bh1, bl0, bl1);
            }
        }
    }
    // epilogue: gelu(+gb1) . gW2, reduce, sigmoid
    float pr[4] = {0, 0, 0, 0};
#pragma unroll
    for (int nf = 0; nf < 4; nf++) {
        int c0 = warp_n + nf * 8 + 2 * t;
        float2 bb = *(const float2*)&gb1[c0];
        float2 ww = *(const float2*)&gW2[c0];
#pragma unroll
        for (int mf = 0; mf < 2; mf++) {
            pr[mf * 2 + 0] += gelu_f(acc[mf][nf][0] + bb.x) * ww.x
                            + gelu_f(acc[mf][nf][1] + bb.y) * ww.y;
            pr[mf * 2 + 1] += gelu_f(acc[mf][nf][2] + bb.x) * ww.x
                            + gelu_f(acc[mf][nf][3] + bb.y) * ww.y;
        }
    }
#pragma unroll
    for (int j = 0; j < 4; j++) {
        pr[j] += __shfl_xor_sync(0xffffffffu, pr[j], 1);
        pr[j] += __shfl_xor_sync(0xffffffffu, pr[j], 2);
    }
    if (t == 0) {
        int nw = wid & 1;
        sred[warp_m + g][nw]      = pr[0];
        sred[warp_m + 8 + g][nw]  = pr[1];
        sred[warp_m + 16 + g][nw] = pr[2];
        sred[warp_m + 24 + g][nw] = pr[3];
    }
    __syncthreads();
    if (tid < 128)
        out[(size_t)Bn * 16 + brow + tid] = sigmoid_f(sred[tid][0] + sred[tid][1] + gb2[0]);
}

// ---------------- plane layernorm (hi/lo packed ys) ----------------
__device__ __forceinline__ void block_ln_pl(uint32_t* yh, uint32_t* yl,
                                            const float* __restrict__ g_,
                                            const float* __restrict__ be_,
                                            int wid, int lane) {
    float gv[8], bv[8];
#pragma unroll
    for (int j = 0; j < 4; j++) {
        float2 gg = *(const float2*)&g_[2 * (lane + 32 * j)];
        float2 bb = *(const float2*)&be_[2 * (lane + 32 * j)];
        gv[2 * j] = gg.x; gv[2 * j + 1] = gg.y;
        bv[2 * j] = bb.x; bv[2 * j + 1] = bb.y;
    }
#pragma unroll
    for (int rr = 0; rr < 8; rr++) {
        int r = wid * 8 + rr;
        float v[8]; float s = 0.0f, s2 = 0.0f;
#pragma unroll
        for (int j = 0; j < 4; j++) {
            float2 a = unpk(yh[r * YSW + lane + 32 * j]);
            float2 b = unpk(yl[r * YSW + lane + 32 * j]);
            v[2 * j] = a.x + b.x; v[2 * j + 1] = a.y + b.y;
            s  += v[2 * j] + v[2 * j + 1];
            s2 += v[2 * j] * v[2 * j] + v[2 * j + 1] * v[2 * j + 1];
        }
#pragma unroll
        for (int o = 16; o > 0; o >>= 1) {
            s  += __shfl_xor_sync(0xffffffffu, s,  o);
            s2 += __shfl_xor_sync(0xffffffffu, s2, o);
        }
        float m   = s * (1.0f / HDn);
        float var = s2 * (1.0f / HDn) - m * m;
        float rv  = rsqrtf(var + 1e-5f);
#pragma unroll
        for (int j = 0; j < 4; j++) {
            float w0 = (v[2 * j] - m) * rv * gv[2 * j] + bv[2 * j];
            float w1 = (v[2 * j + 1] - m) * rv * gv[2 * j + 1] + bv[2 * j + 1];
            uint32_t lo, hi = packsplit(w0, w1, lo);
            yh[r * YSW + lane + 32 * j] = hi;
            yl[r * YSW + lane + 32 * j] = lo;
        }
    }
}

// ---------------- fused ODE step, split-bf16 hidden layers ----------------
// 64 rows/block, 256 threads, 8 warps (2Mx4N, warp 32x64)
__global__ void __launch_bounds__(256, 1) step_kernel(
    const float* __restrict__ W0,  const float* __restrict__ g0,
    const float* __restrict__ be0, const float* __restrict__ br,
    const float* __restrict__ gr,  const float* __restrict__ ber,
    const float* __restrict__ Wout, const float* __restrict__ bout,
    const int* __restrict__ n_steps_p, int step) {
    extern __shared__ uint32_t sp[];
    uint32_t* ysh = sp;                       // 64*132
    uint32_t* ysl = ysh + 64 * YSW;           // 64*132
    uint32_t* wt  = ysl + 64 * YSW;           // 2*4096
    float* Xs   = (float*)(wt + 2 * 4096);    // 64*16
    float* xis  = Xs + 64 * 16;               // 64*6
    float* temb = xis + 64 * 6;               // 64

    int ns = *n_steps_p;
    if (step >= ns) return;
    float dt = 1.0f / (float)ns;
    float tval = (float)step * dt;

    int tid = threadIdx.x;
    int brow = blockIdx.x * 64;
    int wid = tid >> 5, lane = tid & 31;
    int g = lane >> 2, t = lane & 3;
    int warp_m = (wid >> 2) * 32, warp_n = (wid & 3) * 64;

    // prefetch layer-0 chunk-0 weights (overlaps phases 0-1)
#pragma unroll
    for (int q = 0; q < 4; q++) {
        int f = (tid + q * 256) * 4;
        int p = f >> 11, off = f & 2047;
        const uint32_t* src = (p ? g_Wrl : g_Wrh) + off;
        CPA16(sm_u32(&wt[f]), src);
    }
    CPCOMMIT;

    // phase 0: temb + per-row log_se3
    if (tid < 64) {
        int j = tid & 31;
        float freq = expf(-(float)j * (logf(10000.0f) / 31.0f));
        float e = tval * freq;
        temb[tid] = (tid < 32) ? sinf(e) : cosf(e);
        float X[16];
#pragma unroll
        for (int q = 0; q < 16; q++) {
            X[q] = g_X[(size_t)(brow + tid) * 16 + q];
            Xs[tid * 16 + q] = X[q];
        }
        float xi[6];
        log_se3_dev(X, xi);
#pragma unroll
        for (int q = 0; q < 6; q++) xis[tid * 6 + q] = xi[q];
    }
    __syncthreads();

    // phase 1: input layer; thread owns word-column wc for 32 rows
    {
        int wc = tid & 127;
        int rb = (tid >> 7) * 32;
        float tc0 = 0.0f, tc1 = 0.0f;
#pragma unroll 8
        for (int d = 0; d < 64; d++) {
            float2 w2 = *(const float2*)&W0[(size_t)(4102 + d) * HDn + 2 * wc];
            tc0 += temb[d] * w2.x; tc1 += temb[d] * w2.y;
        }
        float2 w0xi[6];
#pragma unroll
        for (int j = 0; j < 6; j++)
            w0xi[j] = *(const float2*)&W0[(size_t)(4096 + j) * HDn + 2 * wc];
        for (int r0 = 0; r0 < 32; r0++) {
            int r = rb + r0;
            float2 h0 = *(const float2*)&g_H0[(size_t)(brow + r) * HDn + 2 * wc];
            float v0 = h0.x + tc0, v1 = h0.y + tc1;
#pragma unroll
            for (int j = 0; j < 6; j++) {
                float xv = xis[r * 6 + j];
                v0 += xv * w0xi[j].x; v1 += xv * w0xi[j].y;
            }
            uint32_t lo, hi = packsplit(gelu_f(v0), gelu_f(v1), lo);
            ysh[r * YSW + wc] = hi; ysl[r * YSW + wc] = lo;
        }
    }
    __syncthreads();
    block_ln_pl(ysh, ysl, g0, be0, wid, lane);
    __syncthreads();

    // phase 2: 3 hidden layers, flat chunk loop gc = l*16 + ch
    float acc[2][8][4];
    for (int gc = 0; gc < 48; gc++) {
        int l = gc >> 4, ch = gc & 15, buf = gc & 1;
        if (ch == 0) {
#pragma unroll
            for (int mf = 0; mf < 2; mf++)
#pragma unroll
                for (int nf = 0; nf < 8; nf++)
#pragma unroll
                    for (int q = 0; q < 4; q++) acc[mf][nf][q] = 0.0f;
        }
        CPWAIT0;
        __syncthreads();
        if (gc + 1 < 48) {
            int nb = (gc + 1) & 1;
#pragma unroll
            for (int q = 0; q < 4; q++) {
                int f = (tid + q * 256) * 4;
                int p = f >> 11, off = f & 2047;
                const uint32_t* src = (p ? g_Wrl : g_Wrh) + (size_t)(gc + 1) * 2048 + off;
                CPA16(sm_u32(&wt[nb * 4096 + f]), src);
            }
            CPCOMMIT;
        }
        // compute chunk
        {
            uint32_t ah[2][4], al[2][4];
#pragma unroll
            for (int mf = 0; mf < 2; mf++) {
                int b0 = (warp_m + mf * 16 + g) * YSW + ch * 8;
                ah[mf][0] = ysh[b0 + t];     ah[mf][1] = ysh[b0 + 8 * YSW + t];
                ah[mf][2] = ysh[b0 + t + 4]; ah[mf][3] = ysh[b0 + 8 * YSW + t + 4];
                al[mf][0] = ysl[b0 + t];     al[mf][1] = ysl[b0 + 8 * YSW + t];
                al[mf][2] = ysl[b0 + t + 4]; al[mf][3] = ysl[b0 + 8 * YSW + t + 4];
            }
            const uint32_t* Bh = wt + buf * 4096;
#pragma unroll
            for (int nf = 0; nf < 8; nf++) {
                int nn = (warp_n + nf * 8 + g) * 8;
                uint32_t bh0 = Bh[nn + t], bh1 = Bh[nn + t + 4];
                uint32_t bl0 = Bh[2048 + nn + t], bl1 = Bh[2048 + nn + t + 4];
                mma3(acc[0][nf], ah[0], al[0], bh0, bh1, bl0, bl1);
                mma3(acc[1][nf], ah[1], al[1], bh0, bh1, bl0, bl1);
            }
        }
        if (ch == 15) {
            __syncthreads();
            // epilogue: gelu(acc + br[l]) -> ys planes
#pragma unroll
            for (int nf = 0; nf < 8; nf++) {
                int c0 = warp_n + nf * 8 + 2 * t;
                float2 bb = *(const float2*)&br[l * HDn + c0];
                int wcw = (warp_n >> 1) + nf * 4 + t;
#pragma unroll
                for (int mf = 0; mf < 2; mf++) {
                    int r0 = warp_m + mf * 16 + g;
                    uint32_t lo, hi;
                    hi = packsplit(gelu_f(acc[mf][nf][0] + bb.x),
                                   gelu_f(acc[mf][nf][1] + bb.y), lo);
                    ysh[r0 * YSW + wcw] = hi; ysl[r0 * YSW + wcw] = lo;
                    hi = packsplit(gelu_f(acc[mf][nf][2] + bb.x),
                                   gelu_f(acc[mf][nf][3] + bb.y), lo);
                    ysh[(r0 + 8) * YSW + wcw] = hi; ysl[(r0 + 8) * YSW + wcw] = lo;
                }
            }
            __syncthreads();
            block_ln_pl(ysh, ysl, gr + l * HDn, ber + l * HDn, wid, lane);
            __syncthreads();
        }
    }

    // phase 3: v = y @ Wout + bout ; X = X @ exp_se3(dt*v)
    for (int rr = 0; rr < 8; rr++) {
        int r = wid * 8 + rr;
        float p[6] = {0, 0, 0, 0, 0, 0};
        for (int wc = lane; wc < 128; wc += 32) {
            float2 a = unpk(ysh[r * YSW + wc]);
            float2 b = unpk(ysl[r * YSW + wc]);
            float v0 = a.x + b.x, v1 = a.y + b.y;
            const float* w0p = Wout + (2 * wc) * 6;
#pragma unroll
            for (int j = 0; j < 6; j++) p[j] += v0 * w0p[j] + v1 * w0p[6 + j];
        }
#pragma unroll
        for (int j = 0; j < 6; j++)
#pragma unroll
            for (int o = 16; o > 0; o >>= 1)
                p[j] += __shfl_xor_sync(0xffffffffu, p[j], o);
        if (lane == 0) {
            float xi[6];
#pragma unroll
            for (int j = 0; j < 6; j++) xi[j] = dt * (p[j] + bout[j]);
            float M[16];
            exp_se3_dev(xi, M);
            const float* Xo = &Xs[r * 16];
            float Xn[16];
#pragma unroll
            for (int i = 0; i < 4; i++)
#pragma unroll
                for (int j = 0; j < 4; j++) {
                    float s = 0.0f;
#pragma unroll
                    for (int k = 0; k < 4; k++) s += Xo[i * 4 + k] * M[k * 4 + j];
                    Xn[i * 4 + j] = s;
                }
#pragma unroll
            for (int q = 0; q < 16; q++) g_X[(size_t)(brow + r) * 16 + q] = Xn[q];
        }
    }
}

// ---------------- final copy ----------------
__global__ void copy_x_kernel(float* __restrict__ out) {
    int i = blockIdx.x * blockDim.x + threadIdx.x;
    if (i < Bn * 16) out[i] = g_X[i];
}

// ---------------- launch ----------------
extern "C" void kernel_launch(void* const* d_in, const int* in_sizes, int n_in,
                              void* d_out, int out_size) {
    const float* h    = (const float*)d_in[0];
    const float* xi0  = (const float*)d_in[1];
    const float* W0   = (const float*)d_in[2];
    const float* b0   = (const float*)d_in[3];
    const float* g0   = (const float*)d_in[4];
    const float* be0  = (const float*)d_in[5];
    const float* Wr   = (const float*)d_in[6];
    const float* br   = (const float*)d_in[7];
    const float* gr   = (const float*)d_in[8];
    const float* ber  = (const float*)d_in[9];
    const float* Wout = (const float*)d_in[10];
    const float* bout = (const float*)d_in[11];
    const float* gW1  = (const float*)d_in[12];
    const float* gb1  = (const float*)d_in[13];
    const float* gW2  = (const float*)d_in[14];
    const float* gb2  = (const float*)d_in[15];
    const int*   nst  = (const int*)d_in[16];
    float* out = (float*)d_out;

    const int H0_SMEM   = (2 * 128 * APh0 + 2 * 8192) * 4;
    const int STEP_SMEM = (2 * 64 * YSW + 2 * 4096 + 64 * 16 + 64 * 6 + 64) * 4;
    cudaFuncSetAttribute(gemm_h0_kernel, cudaFuncAttributeMaxDynamicSharedMemorySize, H0_SMEM);
    cudaFuncSetAttribute(step_kernel, cudaFuncAttributeMaxDynamicSharedMemorySize, STEP_SMEM);

    prep_w0<<<2048, 256>>>(W0);
    prep_wr<<<384, 256>>>(Wr);
    prep_g1<<<512, 256>>>(gW1);
    init_kernel<<<Bn / 256, 256>>>(xi0);
    gemm_h0_kernel<<<Bn / 128, 512, H0_SMEM>>>(h, b0);
    gripper_kernel<<<Bn / 128, 256>>>(h, gb1, gW2, gb2, out);
    for (int s = 0; s < 10; s++)
        step_kernel<<<Bn / 64, 256, STEP_SMEM>>>(W0, g0, be0, br, gr, ber,
                                                 Wout, bout, nst, s);
    copy_x_kernel<<<(Bn * 16) / 256, 256>>>(out);
}

// round 11
// speedup vs baseline: 1.3480x; 1.3480x over previous
#include <cuda_runtime.h>
#include <math.h>
#include <stdint.h>

#define Bn   16384
#define HIDn 4096
#define HDn  256
#define YS  260   // ys row stride (words)
#define WTS 264   // weight tile row stride (words)

// ---------------- scratch ----------------
__device__ float g_H0[Bn * HDn];   // h @ W0[:4096] + b0
__device__ float g_X[Bn * 16];     // SE(3) state
__device__ uint32_t g_Wr32[48 * 16 * WTS];  // Wr pre-cvt tf32, smem-identical layout

// ---------------- helpers ----------------
__device__ __forceinline__ float gelu_f(float x) {
    return 0.5f * x * (1.0f + erff(x * 0.70710678118654752f));
}
__device__ __forceinline__ float sigmoid_f(float x) {
    return 1.0f / (1.0f + expf(-x));
}
__device__ __forceinline__ uint32_t f2tf32(float x) {
    uint32_t r;
    asm("cvt.rna.tf32.f32 %0, %1;" : "=r"(r) : "f"(x));
    return r;
}
__device__ __forceinline__ void mma_tf32(float* c, uint32_t a0, uint32_t a1,
                                         uint32_t a2, uint32_t a3,
                                         uint32_t b0, uint32_t b1) {
    asm volatile(
        "mma.sync.aligned.m16n8k8.row.col.f32.tf32.tf32.f32 "
        "{%0,%1,%2,%3}, {%4,%5,%6,%7}, {%8,%9}, {%0,%1,%2,%3};"
        : "+f"(c[0]), "+f"(c[1]), "+f"(c[2]), "+f"(c[3])
        : "r"(a0), "r"(a1), "r"(a2), "r"(a3), "r"(b0), "r"(b1));
}
__device__ __forceinline__ uint32_t sm_u32(const void* p) {
    return (uint32_t)__cvta_generic_to_shared(p);
}
#define CPA16(d, s) asm volatile("cp.async.cg.shared.global [%0],[%1],16;" ::"r"(d), "l"(s))
#define CPCOMMIT    asm volatile("cp.async.commit_group;")
#define CPWAIT0     asm volatile("cp.async.wait_group 0;" ::: "memory")

__device__ __forceinline__ void exp_se3_dev(const float* xi, float* X) {
    float wx = xi[0], wy = xi[1], wz = xi[2];
    float vx = xi[3], vy = xi[4], vz = xi[5];
    float th2 = wx * wx + wy * wy + wz * wz + 1e-20f;
    float th  = sqrtf(th2);
    bool small = th < 1e-3f;
    float ths = small ? 1.0f : th;
    float s = sinf(ths), c = cosf(ths);
    float A  = small ? (1.0f - th2 / 6.0f)          : (s / ths);
    float Bc = small ? (0.5f - th2 / 24.0f)         : ((1.0f - c) / (ths * ths));
    float Cc = small ? (1.0f / 6.0f - th2 / 120.0f) : ((ths - s) / (ths * ths * ths));
    float wx2 = wx * wx, wy2 = wy * wy, wz2 = wz * wz;
    float xy = wx * wy, xz = wx * wz, yz = wy * wz;
    float R00 = 1.0f - Bc * (wy2 + wz2), R01 = -A * wz + Bc * xy, R02 =  A * wy + Bc * xz;
    float R10 =  A * wz + Bc * xy, R11 = 1.0f - Bc * (wx2 + wz2), R12 = -A * wx + Bc * yz;
    float R20 = -A * wy + Bc * xz, R21 =  A * wx + Bc * yz, R22 = 1.0f - Bc * (wx2 + wy2);
    float V00 = 1.0f - Cc * (wy2 + wz2), V01 = -Bc * wz + Cc * xy, V02 =  Bc * wy + Cc * xz;
    float V10 =  Bc * wz + Cc * xy, V11 = 1.0f - Cc * (wx2 + wz2), V12 = -Bc * wx + Cc * yz;
    float V20 = -Bc * wy + Cc * xz, V21 =  Bc * wx + Cc * yz, V22 = 1.0f - Cc * (wx2 + wy2);
    X[0] = R00; X[1] = R01; X[2]  = R02; X[3]  = V00 * vx + V01 * vy + V02 * vz;
    X[4] = R10; X[5] = R11; X[6]  = R12; X[7]  = V10 * vx + V11 * vy + V12 * vz;
    X[8] = R20; X[9] = R21; X[10] = R22; X[11] = V20 * vx + V21 * vy + V22 * vz;
    X[12] = 0.0f; X[13] = 0.0f; X[14] = 0.0f; X[15] = 1.0f;
}

__device__ __forceinline__ void log_se3_dev(const float* X, float* xi) {
    float R00 = X[0], R01 = X[1], R02 = X[2],  px = X[3];
    float R10 = X[4], R11 = X[5], R12 = X[6],  py = X[7];
    float R20 = X[8], R21 = X[9], R22 = X[10], pz = X[11];
    float tr = R00 + R11 + R22;
    float cc = fminf(fmaxf((tr - 1.0f) * 0.5f, -1.0f + 1e-7f), 1.0f - 1e-7f);
    float th = acosf(cc);
    bool small = th < 1e-3f;
    float ths = small ? 1.0f : th;
    float sn = sinf(ths), csn = cosf(ths);
    float fac = small ? (0.5f + th * th / 12.0f) : (ths / (2.0f * sn));
    float wx = fac * (R21 - R12);
    float wy = fac * (R02 - R20);
    float wz = fac * (R10 - R01);
    float D = small ? (1.0f / 12.0f)
                    : ((1.0f - ths * sn / (2.0f * (1.0f - csn))) / (ths * ths));
    float wx2 = wx * wx, wy2 = wy * wy, wz2 = wz * wz;
    float xy = wx * wy, xz = wx * wz, yz = wy * wz;
    float V00 = 1.0f - D * (wy2 + wz2), V01 =  0.5f * wz + D * xy, V02 = -0.5f * wy + D * xz;
    float V10 = -0.5f * wz + D * xy, V11 = 1.0f - D * (wx2 + wz2), V12 =  0.5f * wx + D * yz;
    float V20 =  0.5f * wy + D * xz, V21 = -0.5f * wx + D * yz, V22 = 1.0f - D * (wx2 + wy2);
    xi[0] = wx; xi[1] = wy; xi[2] = wz;
    xi[3] = V00 * px + V01 * py + V02 * pz;
    xi[4] = V10 * px + V11 * py + V12 * pz;
    xi[5] = V20 * px + V21 * py + V22 * pz;
}

// ---------------- prep: Wr -> tf32, smem-layout-identical ----------------
__global__ void prep_wr32(const float* __restrict__ Wr) {
    int w = blockIdx.x * 256 + threadIdx.x;       // 196608
    int n = w & 255;
    int row = w >> 8;                             // 0..767
    int k = row & 15, gc = row >> 4;
    int l = gc >> 4, ch = gc & 15;
    int kk = ch * 16 + k;
    g_Wr32[gc * (16 * WTS) + k * WTS + n] =
        f2tf32(Wr[(size_t)l * HDn * HDn + (size_t)kk * HDn + n]);
}

// ---------------- init: X0 = exp_se3(0.1 * xi0) ----------------
__global__ void init_kernel(const float* __restrict__ xi0) {
    int r = blockIdx.x * blockDim.x + threadIdx.x;
    if (r >= Bn) return;
    float xi[6];
#pragma unroll
    for (int j = 0; j < 6; j++) xi[j] = 0.1f * xi0[r * 6 + j];
    float X[16];
    exp_se3_dev(xi, X);
#pragma unroll
    for (int j = 0; j < 16; j++) g_X[(size_t)r * 16 + j] = X[j];
}

// ---------------- H0 = h @ W0[:4096,:] + b0, tf32 (R2, known good) ----------------
#define AP 36
#define BP 136
__global__ void __launch_bounds__(256) gemm_h0_kernel(
    const float* __restrict__ h, const float* __restrict__ W0, const float* __restrict__ b0) {
    __shared__ __align__(16) uint32_t As[128 * AP];
    __shared__ __align__(16) uint32_t Bs[32 * BP];
    int brow = blockIdx.x * 128;
    int n0   = blockIdx.y * 128;
    int tid  = threadIdx.x;
    int wid  = tid >> 5, lane = tid & 31;
    int g = lane >> 2, t = lane & 3;
    int warp_m = (wid >> 1) * 32;
    int warp_n = (wid & 1) * 64;

    float acc[2][8][4];
#pragma unroll
    for (int mf = 0; mf < 2; mf++)
#pragma unroll
        for (int nf = 0; nf < 8; nf++)
#pragma unroll
            for (int q = 0; q < 4; q++) acc[mf][nf][q] = 0.0f;

    for (int k0 = 0; k0 < HIDn; k0 += 32) {
#pragma unroll
        for (int q = 0; q < 4; q++) {
            int f = tid + q * 256;
            int row = f >> 3, c4 = (f & 7) * 4;
            float4 v = *(const float4*)(h + (size_t)(brow + row) * HIDn + k0 + c4);
            uint4 u = make_uint4(f2tf32(v.x), f2tf32(v.y), f2tf32(v.z), f2tf32(v.w));
            *(uint4*)&As[row * AP + c4] = u;
        }
#pragma unroll
        for (int q = 0; q < 4; q++) {
            int f = tid + q * 256;
            int row = f >> 5, c4 = (f & 31) * 4;
            float4 v = *(const float4*)(W0 + (size_t)(k0 + row) * HDn + n0 + c4);
            uint4 u = make_uint4(f2tf32(v.x), f2tf32(v.y), f2tf32(v.z), f2tf32(v.w));
            *(uint4*)&Bs[row * BP + c4] = u;
        }
        __syncthreads();
#pragma unroll
        for (int k8 = 0; k8 < 4; k8++) {
            int kb = k8 * 8;
            uint32_t a[2][4];
#pragma unroll
            for (int mf = 0; mf < 2; mf++) {
                int r0 = warp_m + mf * 16 + g;
                a[mf][0] = As[r0 * AP + kb + t];
                a[mf][1] = As[(r0 + 8) * AP + kb + t];
                a[mf][2] = As[r0 * AP + kb + t + 4];
                a[mf][3] = As[(r0 + 8) * AP + kb + t + 4];
            }
#pragma unroll
            for (int nf = 0; nf < 8; nf++) {
                int nn = warp_n + nf * 8 + g;
                uint32_t bb0 = Bs[(kb + t) * BP + nn];
                uint32_t bb1 = Bs[(kb + t + 4) * BP + nn];
                mma_tf32(acc[0][nf], a[0][0], a[0][1], a[0][2], a[0][3], bb0, bb1);
                mma_tf32(acc[1][nf], a[1][0], a[1][1], a[1][2], a[1][3], bb0, bb1);
            }
        }
        __syncthreads();
    }
#pragma unroll
    for (int mf = 0; mf < 2; mf++) {
        int r0 = brow + warp_m + mf * 16 + g;
#pragma unroll
        for (int nf = 0; nf < 8; nf++) {
            int c0 = n0 + warp_n + nf * 8 + 2 * t;
            float bb0 = b0[c0], bb1 = b0[c0 + 1];
            *(float2*)&g_H0[(size_t)r0 * HDn + c0] =
                make_float2(acc[mf][nf][0] + bb0, acc[mf][nf][1] + bb1);
            *(float2*)&g_H0[(size_t)(r0 + 8) * HDn + c0] =
                make_float2(acc[mf][nf][2] + bb0, acc[mf][nf][3] + bb1);
        }
    }
}

// ---------------- gripper via tf32 mma ----------------
// block 128M x 64N, 256 thr, 8 warps (4M x 2N), warp 32x32, k-tile 32
#define BPG 68
__global__ void __launch_bounds__(256) gripper_kernel(
    const float* __restrict__ h, const float* __restrict__ gW1,
    const float* __restrict__ gb1, const float* __restrict__ gW2,
    const float* __restrict__ gb2, float* __restrict__ out) {
    __shared__ __align__(16) uint32_t As[128 * AP];
    __shared__ __align__(16) uint32_t Bs[32 * BPG];
    __shared__ float sred[128][2];
    int brow = blockIdx.x * 128;
    int tid = threadIdx.x, wid = tid >> 5, lane = tid & 31;
    int g = lane >> 2, t = lane & 3;
    int warp_m = (wid >> 1) * 32, warp_n = (wid & 1) * 32;

    float acc[2][4][4];
#pragma unroll
    for (int mf = 0; mf < 2; mf++)
#pragma unroll
        for (int nf = 0; nf < 4; nf++)
#pragma unroll
            for (int q = 0; q < 4; q++) acc[mf][nf][q] = 0.0f;

    for (int k0 = 0; k0 < HIDn; k0 += 32) {
#pragma unroll
        for (int q = 0; q < 4; q++) {
            int f = tid + q * 256;
            int row = f >> 3, c4 = (f & 7) * 4;
            float4 v = *(const float4*)(h + (size_t)(brow + row) * HIDn + k0 + c4);
            uint4 u = make_uint4(f2tf32(v.x), f2tf32(v.y), f2tf32(v.z), f2tf32(v.w));
            *(uint4*)&As[row * AP + c4] = u;
        }
#pragma unroll
        for (int q = 0; q < 2; q++) {
            int f = tid + q * 256;
            int row = f >> 4, c4 = (f & 15) * 4;
            float4 v = *(const float4*)(gW1 + (size_t)(k0 + row) * 64 + c4);
            uint4 u = make_uint4(f2tf32(v.x), f2tf32(v.y), f2tf32(v.z), f2tf32(v.w));
            *(uint4*)&Bs[row * BPG + c4] = u;
        }
        __syncthreads();
#pragma unroll
        for (int k8 = 0; k8 < 4; k8++) {
            int kb = k8 * 8;
            uint32_t a[2][4];
#pragma unroll
            for (int mf = 0; mf < 2; mf++) {
                int r0 = warp_m + mf * 16 + g;
                a[mf][0] = As[r0 * AP + kb + t];
                a[mf][1] = As[(r0 + 8) * AP + kb + t];
                a[mf][2] = As[r0 * AP + kb + t + 4];
                a[mf][3] = As[(r0 + 8) * AP + kb + t + 4];
            }
#pragma unroll
            for (int nf = 0; nf < 4; nf++) {
                int nn = warp_n + nf * 8 + g;
                uint32_t bb0 = Bs[(kb + t) * BPG + nn];
                uint32_t bb1 = Bs[(kb + t + 4) * BPG + nn];
                mma_tf32(acc[0][nf], a[0][0], a[0][1], a[0][2], a[0][3], bb0, bb1);
                mma_tf32(acc[1][nf], a[1][0], a[1][1], a[1][2], a[1][3], bb0, bb1);
            }
        }
        __syncthreads();
    }
    // epilogue: gelu(+gb1) . gW2, reduce, sigmoid
    float pr[4] = {0, 0, 0, 0};
#pragma unroll
    for (int nf = 0; nf < 4; nf++) {
        int c0 = warp_n + nf * 8 + 2 * t;
        float2 bb = make_float2(gb1[c0], gb1[c0 + 1]);
        float2 ww = make_float2(gW2[c0], gW2[c0 + 1]);
#pragma unroll
        for (int mf = 0; mf < 2; mf++) {
            pr[mf * 2 + 0] += gelu_f(acc[mf][nf][0] + bb.x) * ww.x
                            + gelu_f(acc[mf][nf][1] + bb.y) * ww.y;
            pr[mf * 2 + 1] += gelu_f(acc[mf][nf][2] + bb.x) * ww.x
                            + gelu_f(acc[mf][nf][3] + bb.y) * ww.y;
        }
    }
#pragma unroll
    for (int j = 0; j < 4; j++) {
        pr[j] += __shfl_xor_sync(0xffffffffu, pr[j], 1);
        pr[j] += __shfl_xor_sync(0xffffffffu, pr[j], 2);
    }
    if (t == 0) {
        int nw = wid & 1;
        sred[warp_m + g][nw]      = pr[0];
        sred[warp_m + 8 + g][nw]  = pr[1];
        sred[warp_m + 16 + g][nw] = pr[2];
        sred[warp_m + 24 + g][nw] = pr[3];
    }
    __syncthreads();
    if (tid < 128)
        out[(size_t)Bn * 16 + brow + tid] = sigmoid_f(sred[tid][0] + sred[tid][1] + gb2[0]);
}

// ---------------- layernorm on tf32-bit ys ----------------
__device__ __forceinline__ void block_ln32(uint32_t* ys, const float* __restrict__ g_,
                                           const float* __restrict__ be_, int wid, int lane) {
    float gv[8], bv[8];
#pragma unroll
    for (int j = 0; j < 8; j++) { gv[j] = g_[lane + j * 32]; bv[j] = be_[lane + j * 32]; }
#pragma unroll
    for (int rr = 0; rr < 8; rr++) {
        int r = wid * 8 + rr;
        float v[8]; float s = 0.0f, s2 = 0.0f;
#pragma unroll
        for (int j = 0; j < 8; j++) {
            v[j] = __uint_as_float(ys[r * YS + lane + j * 32]);
            s += v[j]; s2 += v[j] * v[j];
        }
#pragma unroll
        for (int o = 16; o > 0; o >>= 1) {
            s  += __shfl_xor_sync(0xffffffffu, s,  o);
            s2 += __shfl_xor_sync(0xffffffffu, s2, o);
        }
        float m   = s * (1.0f / HDn);
        float var = s2 * (1.0f / HDn) - m * m;
        float rv  = rsqrtf(var + 1e-5f);
#pragma unroll
        for (int j = 0; j < 8; j++)
            ys[r * YS + lane + j * 32] = f2tf32((v[j] - m) * rv * gv[j] + bv[j]);
    }
}

// ---------------- fused ODE step: tf32 ys + cp.async weight stream ----------------
// 64 rows/block, 256 threads, 8 warps (2M x 4N), warp tile 32x64
__global__ void __launch_bounds__(256, 2) step_kernel(
    const float* __restrict__ W0,  const float* __restrict__ g0,
    const float* __restrict__ be0, const float* __restrict__ br,
    const float* __restrict__ gr,  const float* __restrict__ ber,
    const float* __restrict__ Wout, const float* __restrict__ bout,
    const int* __restrict__ n_steps_p, int step) {
    extern __shared__ uint32_t sp[];
    uint32_t* ys = sp;                        // 64*260 (tf32 bits)
    uint32_t* wt = ys + 64 * YS;              // 2 * 16*264 double buffer
    float* Xs   = (float*)(wt + 2 * 16 * WTS);  // 64*16
    float* xis  = Xs + 64 * 16;               // 64*6
    float* temb = xis + 64 * 6;               // 64

    int ns = *n_steps_p;
    if (step >= ns) return;
    float dt = 1.0f / (float)ns;
    float tval = (float)step * dt;

    int tid = threadIdx.x;
    int brow = blockIdx.x * 64;
    int wid = tid >> 5, lane = tid & 31;
    int g = lane >> 2, t = lane & 3;
    int warp_m = (wid >> 2) * 32, warp_n = (wid & 3) * 64;

    // prefetch chunk 0 weights (overlaps phases 0-1)
#pragma unroll
    for (int q = 0; q < 4; q++) {
        int idx = tid + q * 256;               // 0..1023
        int row = idx >> 6, c4 = (idx & 63) * 4;
        CPA16(sm_u32(&wt[row * WTS + c4]), g_Wr32 + row * WTS + c4);
    }
    CPCOMMIT;

    // phase 0: temb + per-row log_se3
    if (tid < 64) {
        int j = tid & 31;
        float freq = expf(-(float)j * (logf(10000.0f) / 31.0f));
        float e = tval * freq;
        temb[tid] = (tid < 32) ? sinf(e) : cosf(e);
        float X[16];
#pragma unroll
        for (int q = 0; q < 16; q++) {
            X[q] = g_X[(size_t)(brow + tid) * 16 + q];
            Xs[tid * 16 + q] = X[q];
        }
        float xi[6];
        log_se3_dev(X, xi);
#pragma unroll
        for (int q = 0; q < 6; q++) xis[tid * 6 + q] = xi[q];
    }
    __syncthreads();

    // phase 1: input layer; thread owns column tid for 64 rows, store tf32
    {
        float tc = 0.0f;
#pragma unroll 8
        for (int d = 0; d < 64; d++)
            tc += temb[d] * W0[(size_t)(4102 + d) * HDn + tid];
        float w0xi[6];
#pragma unroll
        for (int j = 0; j < 6; j++) w0xi[j] = W0[(size_t)(4096 + j) * HDn + tid];
        for (int r = 0; r < 64; r++) {
            float v = g_H0[(size_t)(brow + r) * HDn + tid] + tc;
#pragma unroll
            for (int j = 0; j < 6; j++) v += xis[r * 6 + j] * w0xi[j];
            ys[r * YS + tid] = f2tf32(gelu_f(v));
        }
    }
    __syncthreads();
    block_ln32(ys, g0, be0, wid, lane);
    __syncthreads();

    // phase 2: 3 hidden layers, flat 48-chunk loop (gc = l*16 + ch), cp.async pingpong
    float acc[2][8][4];
    for (int gc = 0; gc < 48; gc++) {
        int l = gc >> 4, ch = gc & 15, buf = gc & 1;
        if (ch == 0) {
#pragma unroll
            for (int mf = 0; mf < 2; mf++)
#pragma unroll
                for (int nf = 0; nf < 8; nf++)
#pragma unroll
                    for (int q = 0; q < 4; q++) acc[mf][nf][q] = 0.0f;
        }
        CPWAIT0;
        __syncthreads();
        if (gc + 1 < 48) {
            int nb = (gc + 1) & 1;
            const uint32_t* src = g_Wr32 + (size_t)(gc + 1) * (16 * WTS);
#pragma unroll
            for (int q = 0; q < 4; q++) {
                int idx = tid + q * 256;
                int row = idx >> 6, c4 = (idx & 63) * 4;
                CPA16(sm_u32(&wt[nb * 16 * WTS + row * WTS + c4]), src + row * WTS + c4);
            }
            CPCOMMIT;
        }
        const uint32_t* Bh = wt + buf * 16 * WTS;
#pragma unroll
        for (int k8 = 0; k8 < 2; k8++) {
            int kb = k8 * 8;
            int kcol = ch * 16 + kb;
            uint32_t a[2][4];
#pragma unroll
            for (int mf = 0; mf < 2; mf++) {
                int r0 = warp_m + mf * 16 + g;
                a[mf][0] = ys[r0 * YS + kcol + t];
                a[mf][1] = ys[(r0 + 8) * YS + kcol + t];
                a[mf][2] = ys[r0 * YS + kcol + t + 4];
                a[mf][3] = ys[(r0 + 8) * YS + kcol + t + 4];
            }
#pragma unroll
            for (int nf = 0; nf < 8; nf++) {
                int nn = warp_n + nf * 8 + g;
                uint32_t bb0 = Bh[(kb + t) * WTS + nn];
                uint32_t bb1 = Bh[(kb + t + 4) * WTS + nn];
                mma_tf32(acc[0][nf], a[0][0], a[0][1], a[0][2], a[0][3], bb0, bb1);
                mma_tf32(acc[1][nf], a[1][0], a[1][1], a[1][2], a[1][3], bb0, bb1);
            }
        }
        if (ch == 15) {
            __syncthreads();
#pragma unroll
            for (int nf = 0; nf < 8; nf++) {
                int c0 = warp_n + nf * 8 + 2 * t;
                float bb0 = br[l * HDn + c0], bb1 = br[l * HDn + c0 + 1];
#pragma unroll
                for (int mf = 0; mf < 2; mf++) {
                    int r0 = warp_m + mf * 16 + g;
                    ys[r0 * YS + c0]           = f2tf32(gelu_f(acc[mf][nf][0] + bb0));
                    ys[r0 * YS + c0 + 1]       = f2tf32(gelu_f(acc[mf][nf][1] + bb1));
                    ys[(r0 + 8) * YS + c0]     = f2tf32(gelu_f(acc[mf][nf][2] + bb0));
                    ys[(r0 + 8) * YS + c0 + 1] = f2tf32(gelu_f(acc[mf][nf][3] + bb1));
                }
            }
            __syncthreads();
            block_ln32(ys, gr + l * HDn, ber + l * HDn, wid, lane);
            __syncthreads();
        }
    }

    // phase 3: v = y @ Wout + bout ; X = X @ exp_se3(dt*v)
    for (int rr = 0; rr < 8; rr++) {
        int r = wid * 8 + rr;
        float p[6] = {0, 0, 0, 0, 0, 0};
        for (int c = lane; c < HDn; c += 32) {
            float yv = __uint_as_float(ys[r * YS + c]);
            const float* wp = Wout + c * 6;
#pragma unroll
            for (int j = 0; j < 6; j++) p[j] += yv * wp[j];
        }
#pragma unroll
        for (int j = 0; j < 6; j++)
#pragma unroll
            for (int o = 16; o > 0; o >>= 1)
                p[j] += __shfl_xor_sync(0xffffffffu, p[j], o);
        if (lane == 0) {
            float xi[6];
#pragma unroll
            for (int j = 0; j < 6; j++) xi[j] = dt * (p[j] + bout[j]);
            float M[16];
            exp_se3_dev(xi, M);
            const float* Xo = &Xs[r * 16];
            float Xn[16];
#pragma unroll
            for (int i = 0; i < 4; i++)
#pragma unroll
                for (int j = 0; j < 4; j++) {
                    float s = 0.0f;
#pragma unroll
                    for (int k = 0; k < 4; k++) s += Xo[i * 4 + k] * M[k * 4 + j];
                    Xn[i * 4 + j] = s;
                }
#pragma unroll
            for (int q = 0; q < 16; q++) g_X[(size_t)(brow + r) * 16 + q] = Xn[q];
        }
    }
}

// ---------------- final copy ----------------
__global__ void copy_x_kernel(float* __restrict__ out) {
    int i = blockIdx.x * blockDim.x + threadIdx.x;
    if (i < Bn * 16) out[i] = g_X[i];
}

// ---------------- launch ----------------
extern "C" void kernel_launch(void* const* d_in, const int* in_sizes, int n_in,
                              void* d_out, int out_size) {
    const float* h    = (const float*)d_in[0];
    const float* xi0  = (const float*)d_in[1];
    const float* W0   = (const float*)d_in[2];
    const float* b0   = (const float*)d_in[3];
    const float* g0   = (const float*)d_in[4];
    const float* be0  = (const float*)d_in[5];
    const float* Wr   = (const float*)d_in[6];
    const float* br   = (const float*)d_in[7];
    const float* gr   = (const float*)d_in[8];
    const float* ber  = (const float*)d_in[9];
    const float* Wout = (const float*)d_in[10];
    const float* bout = (const float*)d_in[11];
    const float* gW1  = (const float*)d_in[12];
    const float* gb1  = (const float*)d_in[13];
    const float* gW2  = (const float*)d_in[14];
    const float* gb2  = (const float*)d_in[15];
    const int*   nst  = (const int*)d_in[16];
    float* out = (float*)d_out;

    const int STEP_SMEM = (64 * YS + 2 * 16 * WTS + 64 * 16 + 64 * 6 + 64) * 4; // ~106 KB
    cudaFuncSetAttribute(step_kernel, cudaFuncAttributeMaxDynamicSharedMemorySize, STEP_SMEM);

    prep_wr32<<<768, 256>>>(Wr);
    init_kernel<<<Bn / 256, 256>>>(xi0);
    dim3 g0grid(Bn / 128, 2);
    gemm_h0_kernel<<<g0grid, 256>>>(h, W0, b0);
    gripper_kernel<<<Bn / 128, 256>>>(h, gW1, gb1, gW2, gb2, out);
    for (int s = 0; s < 10; s++)
        step_kernel<<<Bn / 64, 256, STEP_SMEM>>>(W0, g0, be0, br, gr, ber,
                                                 Wout, bout, nst, s);
    copy_x_kernel<<<(Bn * 16) / 256, 256>>>(out);
}

// round 12
// speedup vs baseline: 1.7699x; 1.3130x over previous
#include <cuda_runtime.h>
#include <math.h>
#include <stdint.h>

#define Bn   16384
#define HIDn 4096
#define HDn  256
#define YS   260   // ys row stride (words)

// ---------------- scratch ----------------
__device__ float g_H0[Bn * HDn];   // h @ W0[:4096] + b0
__device__ float g_X[Bn * 16];     // SE(3) state
// frag-ordered tf32 weights:
// step:  pair p = ((gc*2 + k8)*32 + nfg)*32 + lane ; words 2p,2p+1
__device__ uint32_t g_Wr32[48 * 4096];
// fused: pair p = (((tl*4 + cc*2 + k8)*40) + nfg)*32 + lane
__device__ uint32_t g_Wc[128 * 10240];   // W0[:4096,:256] ++ gW1[:, :64]

// ---------------- helpers ----------------
__device__ __forceinline__ float gelu_f(float x) {
    return 0.5f * x * (1.0f + erff(x * 0.70710678118654752f));
}
__device__ __forceinline__ float sigmoid_f(float x) {
    return 1.0f / (1.0f + expf(-x));
}
__device__ __forceinline__ uint32_t f2tf32(float x) {
    uint32_t r;
    asm("cvt.rna.tf32.f32 %0, %1;" : "=r"(r) : "f"(x));
    return r;
}
__device__ __forceinline__ void mma_tf32(float* c, uint32_t a0, uint32_t a1,
                                         uint32_t a2, uint32_t a3,
                                         uint32_t b0, uint32_t b1) {
    asm volatile(
        "mma.sync.aligned.m16n8k8.row.col.f32.tf32.tf32.f32 "
        "{%0,%1,%2,%3}, {%4,%5,%6,%7}, {%8,%9}, {%0,%1,%2,%3};"
        : "+f"(c[0]), "+f"(c[1]), "+f"(c[2]), "+f"(c[3])
        : "r"(a0), "r"(a1), "r"(a2), "r"(a3), "r"(b0), "r"(b1));
}
__device__ __forceinline__ uint32_t sm_u32(const void* p) {
    return (uint32_t)__cvta_generic_to_shared(p);
}
#define MBAR_INIT(addr, cnt) \
    asm volatile("mbarrier.init.shared.b64 [%0], %1;" ::"r"(addr), "r"(cnt) : "memory")
#define MBAR_EXPECT(addr, bytes) \
    asm volatile("mbarrier.arrive.expect_tx.shared.b64 _, [%0], %1;" ::"r"(addr), "r"(bytes) : "memory")
#define BULK_G2S(dst, src, bytes, mbar) \
    asm volatile("cp.async.bulk.shared::cta.global.mbarrier::complete_tx::bytes [%0], [%1], %2, [%3];" \
                 ::"r"(dst), "l"(src), "r"(bytes), "r"(mbar) : "memory")
#define MBAR_WAIT(addr, parity) \
    asm volatile("{\n\t.reg .pred P;\n\tWL%=:\n\tmbarrier.try_wait.parity.shared.b64 P, [%0], %1;\n\t" \
                 "@P bra WD%=;\n\tbra WL%=;\n\tWD%=:\n\t}" ::"r"(addr), "r"(parity) : "memory")

__device__ __forceinline__ void exp_se3_dev(const float* xi, float* X) {
    float wx = xi[0], wy = xi[1], wz = xi[2];
    float vx = xi[3], vy = xi[4], vz = xi[5];
    float th2 = wx * wx + wy * wy + wz * wz + 1e-20f;
    float th  = sqrtf(th2);
    bool small = th < 1e-3f;
    float ths = small ? 1.0f : th;
    float s = sinf(ths), c = cosf(ths);
    float A  = small ? (1.0f - th2 / 6.0f)          : (s / ths);
    float Bc = small ? (0.5f - th2 / 24.0f)         : ((1.0f - c) / (ths * ths));
    float Cc = small ? (1.0f / 6.0f - th2 / 120.0f) : ((ths - s) / (ths * ths * ths));
    float wx2 = wx * wx, wy2 = wy * wy, wz2 = wz * wz;
    float xy = wx * wy, xz = wx * wz, yz = wy * wz;
    float R00 = 1.0f - Bc * (wy2 + wz2), R01 = -A * wz + Bc * xy, R02 =  A * wy + Bc * xz;
    float R10 =  A * wz + Bc * xy, R11 = 1.0f - Bc * (wx2 + wz2), R12 = -A * wx + Bc * yz;
    float R20 = -A * wy + Bc * xz, R21 =  A * wx + Bc * yz, R22 = 1.0f - Bc * (wx2 + wy2);
    float V00 = 1.0f - Cc * (wy2 + wz2), V01 = -Bc * wz + Cc * xy, V02 =  Bc * wy + Cc * xz;
    float V10 =  Bc * wz + Cc * xy, V11 = 1.0f - Cc * (wx2 + wz2), V12 = -Bc * wx + Cc * yz;
    float V20 = -Bc * wy + Cc * xz, V21 =  Bc * wx + Cc * yz, V22 = 1.0f - Cc * (wx2 + wy2);
    X[0] = R00; X[1] = R01; X[2]  = R02; X[3]  = V00 * vx + V01 * vy + V02 * vz;
    X[4] = R10; X[5] = R11; X[6]  = R12; X[7]  = V10 * vx + V11 * vy + V12 * vz;
    X[8] = R20; X[9] = R21; X[10] = R22; X[11] = V20 * vx + V21 * vy + V22 * vz;
    X[12] = 0.0f; X[13] = 0.0f; X[14] = 0.0f; X[15] = 1.0f;
}

__device__ __forceinline__ void log_se3_dev(const float* X, float* xi) {
    float R00 = X[0], R01 = X[1], R02 = X[2],  px = X[3];
    float R10 = X[4], R11 = X[5], R12 = X[6],  py = X[7];
    float R20 = X[8], R21 = X[9], R22 = X[10], pz = X[11];
    float tr = R00 + R11 + R22;
    float cc = fminf(fmaxf((tr - 1.0f) * 0.5f, -1.0f + 1e-7f), 1.0f - 1e-7f);
    float th = acosf(cc);
    bool small = th < 1e-3f;
    float ths = small ? 1.0f : th;
    float sn = sinf(ths), csn = cosf(ths);
    float fac = small ? (0.5f + th * th / 12.0f) : (ths / (2.0f * sn));
    float wx = fac * (R21 - R12);
    float wy = fac * (R02 - R20);
    float wz = fac * (R10 - R01);
    float D = small ? (1.0f / 12.0f)
                    : ((1.0f - ths * sn / (2.0f * (1.0f - csn))) / (ths * ths));
    float wx2 = wx * wx, wy2 = wy * wy, wz2 = wz * wz;
    float xy = wx * wy, xz = wx * wz, yz = wy * wz;
    float V00 = 1.0f - D * (wy2 + wz2), V01 =  0.5f * wz + D * xy, V02 = -0.5f * wy + D * xz;
    float V10 = -0.5f * wz + D * xy, V11 = 1.0f - D * (wx2 + wz2), V12 =  0.5f * wx + D * yz;
    float V20 =  0.5f * wy + D * xz, V21 = -0.5f * wx + D * yz, V22 = 1.0f - D * (wx2 + wy2);
    xi[0] = wx; xi[1] = wy; xi[2] = wz;
    xi[3] = V00 * px + V01 * py + V02 * pz;
    xi[4] = V10 * px + V11 * py + V12 * pz;
    xi[5] = V20 * px + V21 * py + V22 * pz;
}

// ---------------- prep: Wr -> frag-ordered tf32 ----------------
__global__ void prep_wr32(const float* __restrict__ Wr) {
    int p = blockIdx.x * 256 + threadIdx.x;    // 98304 pairs
    int lane = p & 31;
    int rest = p >> 5;
    int nfg = rest & 31;
    int rest2 = rest >> 5;
    int k8 = rest2 & 1, gc = rest2 >> 1;
    int l = gc >> 4, ch = gc & 15;
    int g = lane >> 2, t = lane & 3;
    int w = nfg >> 3, nf = nfg & 7;
    int n = w * 64 + nf * 8 + g;
    int k = ch * 16 + k8 * 8 + t;
    const float* s = Wr + (size_t)l * HDn * HDn + (size_t)k * HDn + n;
    g_Wr32[2 * p]     = f2tf32(s[0]);
    g_Wr32[2 * p + 1] = f2tf32(s[4 * HDn]);
}

// ---------------- prep: [W0 | gW1] -> frag-ordered tf32 ----------------
__global__ void prep_wc(const float* __restrict__ W0, const float* __restrict__ gW1) {
    int p = blockIdx.x * 256 + threadIdx.x;    // 655360 pairs
    int lane = p & 31;
    int rest = p >> 5;
    int nfg = rest % 40;
    int rest2 = rest / 40;
    int k8 = rest2 & 1, cc = (rest2 >> 1) & 1, tl = rest2 >> 2;
    int g = lane >> 2, t = lane & 3;
    int k = tl * 32 + cc * 16 + k8 * 8 + t;
    float s0, s1;
    if (nfg < 32) {
        int w = nfg >> 3, nf = nfg & 7;
        int n = w * 64 + nf * 8 + g;
        s0 = W0[(size_t)k * HDn + n];
        s1 = W0[(size_t)(k + 4) * HDn + n];
    } else {
        int q2 = nfg - 32;
        int w = q2 >> 1, nf2 = q2 & 1;
        int n = w * 16 + nf2 * 8 + g;
        s0 = gW1[(size_t)k * 64 + n];
        s1 = gW1[(size_t)(k + 4) * 64 + n];
    }
    g_Wc[2 * p]     = f2tf32(s0);
    g_Wc[2 * p + 1] = f2tf32(s1);
}

// ---------------- init: X0 = exp_se3(0.1 * xi0) ----------------
__global__ void init_kernel(const float* __restrict__ xi0) {
    int r = blockIdx.x * blockDim.x + threadIdx.x;
    if (r >= Bn) return;
    float xi[6];
#pragma unroll
    for (int j = 0; j < 6; j++) xi[j] = 0.1f * xi0[r * 6 + j];
    float X[16];
    exp_se3_dev(xi, X);
#pragma unroll
    for (int j = 0; j < 16; j++) g_X[(size_t)r * 16 + j] = X[j];
}

// ---------------- fused: H0 = h@W0 + b0  AND  gripper, one h pass ----------------
// grid 128, block 512 (16 warps = 4M x 4N), 128 rows x (256 + 64) cols, k-tile 32
#define AP 36
__global__ void __launch_bounds__(512, 1) fused_h_kernel(
    const float* __restrict__ h, const float* __restrict__ b0,
    const float* __restrict__ gb1, const float* __restrict__ gW2,
    const float* __restrict__ gb2, float* __restrict__ out) {
    extern __shared__ uint32_t sp[];
    uint32_t mb0 = sm_u32(sp), mb1 = mb0 + 8;
    uint32_t* As = sp + 4;                // 2 x 128*36
    uint32_t* Bs = As + 2 * 128 * AP;     // 2 x 10240
    float* sred = (float*)(Bs + 2 * 10240);  // 128 x 4

    int brow = blockIdx.x * 128;
    int tid = threadIdx.x, wid = tid >> 5, lane = tid & 31;
    int g = lane >> 2, t = lane & 3;
    int wm = wid >> 2, wn = wid & 3;
    int warp_m = wm * 32, warp_n = wn * 64;
    int ar = tid >> 2, ac = (tid & 3) * 8;

    float acc[2][8][4];
    float accg[2][2][4];
#pragma unroll
    for (int mf = 0; mf < 2; mf++) {
#pragma unroll
        for (int nf = 0; nf < 8; nf++)
#pragma unroll
            for (int q = 0; q < 4; q++) acc[mf][nf][q] = 0.0f;
#pragma unroll
        for (int nf = 0; nf < 2; nf++)
#pragma unroll
            for (int q = 0; q < 4; q++) accg[mf][nf][q] = 0.0f;
    }

    if (tid == 0) { MBAR_INIT(mb0, 1); MBAR_INIT(mb1, 1); }
    __syncthreads();
    if (tid == 0) {
        MBAR_EXPECT(mb0, 40960);
        BULK_G2S(sm_u32(Bs), (const char*)g_Wc, 40960, mb0);
    }
    float4 a4[2];
    {
        const float* s = h + (size_t)(brow + ar) * HIDn + ac;
        a4[0] = *(const float4*)s; a4[1] = *(const float4*)(s + 4);
    }

    for (int tl = 0; tl < 128; tl++) {
        int buf = tl & 1;
        uint32_t mb = buf ? mb1 : mb0;
        uint32_t mbn = buf ? mb0 : mb1;
        // store A(tl) split into As[buf]
        {
            uint32_t* pa = As + buf * (128 * AP) + ar * AP + ac;
            uint4 u0 = make_uint4(f2tf32(a4[0].x), f2tf32(a4[0].y), f2tf32(a4[0].z), f2tf32(a4[0].w));
            uint4 u1 = make_uint4(f2tf32(a4[1].x), f2tf32(a4[1].y), f2tf32(a4[1].z), f2tf32(a4[1].w));
            *(uint4*)pa = u0;
            *(uint4*)(pa + 4) = u1;
        }
        __syncthreads();
        if (tid == 0 && tl + 1 < 128) {
            MBAR_EXPECT(mbn, 40960);
            BULK_G2S(sm_u32(Bs + (buf ^ 1) * 10240),
                     (const char*)(g_Wc + (size_t)(tl + 1) * 10240), 40960, mbn);
        }
        if (tl + 1 < 128) {
            const float* s = h + (size_t)(brow + ar) * HIDn + (tl + 1) * 32 + ac;
            a4[0] = *(const float4*)s; a4[1] = *(const float4*)(s + 4);
        }
        MBAR_WAIT(mb, (tl >> 1) & 1);
        const uint32_t* Asb = As + buf * (128 * AP);
        const uint32_t* Bsb = Bs + buf * 10240;
#pragma unroll
        for (int cc = 0; cc < 2; cc++) {
#pragma unroll
            for (int k8 = 0; k8 < 2; k8++) {
                int kcol = cc * 16 + k8 * 8;
                uint32_t a[2][4];
#pragma unroll
                for (int mf = 0; mf < 2; mf++) {
                    int r0 = (warp_m + mf * 16 + g) * AP + kcol;
                    a[mf][0] = Asb[r0 + t];
                    a[mf][1] = Asb[r0 + 8 * AP + t];
                    a[mf][2] = Asb[r0 + t + 4];
                    a[mf][3] = Asb[r0 + 8 * AP + t + 4];
                }
                const uint32_t* Bk = Bsb + (cc * 2 + k8) * 40 * 64;
#pragma unroll
                for (int nf = 0; nf < 8; nf++) {
                    uint2 bb = *(const uint2*)&Bk[(wn * 8 + nf) * 64 + lane * 2];
                    mma_tf32(acc[0][nf], a[0][0], a[0][1], a[0][2], a[0][3], bb.x, bb.y);
                    mma_tf32(acc[1][nf], a[1][0], a[1][1], a[1][2], a[1][3], bb.x, bb.y);
                }
#pragma unroll
                for (int nf2 = 0; nf2 < 2; nf2++) {
                    uint2 bb = *(const uint2*)&Bk[(32 + wn * 2 + nf2) * 64 + lane * 2];
                    mma_tf32(accg[0][nf2], a[0][0], a[0][1], a[0][2], a[0][3], bb.x, bb.y);
                    mma_tf32(accg[1][nf2], a[1][0], a[1][1], a[1][2], a[1][3], bb.x, bb.y);
                }
            }
        }
    }
    // H0 epilogue
#pragma unroll
    for (int mf = 0; mf < 2; mf++) {
        int r0 = brow + warp_m + mf * 16 + g;
#pragma unroll
        for (int nf = 0; nf < 8; nf++) {
            int c0 = warp_n + nf * 8 + 2 * t;
            float bb0 = b0[c0], bb1 = b0[c0 + 1];
            *(float2*)&g_H0[(size_t)r0 * HDn + c0] =
                make_float2(acc[mf][nf][0] + bb0, acc[mf][nf][1] + bb1);
            *(float2*)&g_H0[(size_t)(r0 + 8) * HDn + c0] =
                make_float2(acc[mf][nf][2] + bb0, acc[mf][nf][3] + bb1);
        }
    }
    // gripper epilogue: gelu(+gb1) . gW2, reduce over t, then over 4 n-warps
    float pr[4] = {0, 0, 0, 0};
#pragma unroll
    for (int nf2 = 0; nf2 < 2; nf2++) {
        int c0 = wn * 16 + nf2 * 8 + 2 * t;
        float bb0 = gb1[c0], bb1 = gb1[c0 + 1];
        float w0 = gW2[c0], w1 = gW2[c0 + 1];
#pragma unroll
        for (int mf = 0; mf < 2; mf++) {
            pr[mf * 2 + 0] += gelu_f(accg[mf][nf2][0] + bb0) * w0
                            + gelu_f(accg[mf][nf2][1] + bb1) * w1;
            pr[mf * 2 + 1] += gelu_f(accg[mf][nf2][2] + bb0) * w0
                            + gelu_f(accg[mf][nf2][3] + bb1) * w1;
        }
    }
#pragma unroll
    for (int j = 0; j < 4; j++) {
        pr[j] += __shfl_xor_sync(0xffffffffu, pr[j], 1);
        pr[j] += __shfl_xor_sync(0xffffffffu, pr[j], 2);
    }
    __syncthreads();
    if (t == 0) {
        sred[(warp_m + g) * 4 + wn]      = pr[0];
        sred[(warp_m + g + 8) * 4 + wn]  = pr[1];
        sred[(warp_m + 16 + g) * 4 + wn] = pr[2];
        sred[(warp_m + 24 + g) * 4 + wn] = pr[3];
    }
    __syncthreads();
    if (tid < 128) {
        float s = sred[tid * 4] + sred[tid * 4 + 1] + sred[tid * 4 + 2] + sred[tid * 4 + 3];
        out[(size_t)Bn * 16 + brow + tid] = sigmoid_f(s + gb2[0]);
    }
}

// ---------------- layernorm on tf32-bit ys ----------------
__device__ __forceinline__ void block_ln32(uint32_t* ys, const float* __restrict__ g_,
                                           const float* __restrict__ be_, int wid, int lane) {
    float gv[8], bv[8];
#pragma unroll
    for (int j = 0; j < 8; j++) { gv[j] = g_[lane + j * 32]; bv[j] = be_[lane + j * 32]; }
#pragma unroll
    for (int rr = 0; rr < 8; rr++) {
        int r = wid * 8 + rr;
        float v[8]; float s = 0.0f, s2 = 0.0f;
#pragma unroll
        for (int j = 0; j < 8; j++) {
            v[j] = __uint_as_float(ys[r * YS + lane + j * 32]);
            s += v[j]; s2 += v[j] * v[j];
        }
#pragma unroll
        for (int o = 16; o > 0; o >>= 1) {
            s  += __shfl_xor_sync(0xffffffffu, s,  o);
            s2 += __shfl_xor_sync(0xffffffffu, s2, o);
        }
        float m   = s * (1.0f / HDn);
        float var = s2 * (1.0f / HDn) - m * m;
        float rv  = rsqrtf(var + 1e-5f);
#pragma unroll
        for (int j = 0; j < 8; j++)
            ys[r * YS + lane + j * 32] = f2tf32((v[j] - m) * rv * gv[j] + bv[j]);
    }
}

// ---------------- fused ODE step: bulk-TMA weights, frag-order B ----------------
// 64 rows/block, 256 threads, 8 warps (2M x 4N), warp tile 32x64
__global__ void __launch_bounds__(256, 2) step_kernel(
    const float* __restrict__ W0,  const float* __restrict__ g0,
    const float* __restrict__ be0, const float* __restrict__ br,
    const float* __restrict__ gr,  const float* __restrict__ ber,
    const float* __restrict__ Wout, const float* __restrict__ bout,
    const int* __restrict__ n_steps_p, int step) {
    extern __shared__ uint32_t sp[];
    uint32_t mb0 = sm_u32(sp), mb1 = mb0 + 8;
    uint32_t* ys = sp + 4;                    // 64*260 (tf32 bits)
    uint32_t* wt = ys + 64 * YS;              // 2 x 4096 frag-order weights
    float* Xs   = (float*)(wt + 2 * 4096);    // 64*16
    float* xis  = Xs + 64 * 16;               // 64*6
    float* temb = xis + 64 * 6;               // 64

    int ns = *n_steps_p;
    if (step >= ns) return;
    float dt = 1.0f / (float)ns;
    float tval = (float)step * dt;

    int tid = threadIdx.x;
    int brow = blockIdx.x * 64;
    int wid = tid >> 5, lane = tid & 31;
    int g = lane >> 2, t = lane & 3;
    int warp_m = (wid >> 2) * 32, warp_n = (wid & 3) * 64;

    if (tid == 0) { MBAR_INIT(mb0, 1); MBAR_INIT(mb1, 1); }
    __syncthreads();
    if (tid == 0) {
        MBAR_EXPECT(mb0, 16384);
        BULK_G2S(sm_u32(wt), (const char*)g_Wr32, 16384, mb0);
    }

    // phase 0: temb + per-row log_se3
    if (tid < 64) {
        int j = tid & 31;
        float freq = expf(-(float)j * (logf(10000.0f) / 31.0f));
        float e = tval * freq;
        temb[tid] = (tid < 32) ? sinf(e) : cosf(e);
        float X[16];
#pragma unroll
        for (int q = 0; q < 16; q++) {
            X[q] = g_X[(size_t)(brow + tid) * 16 + q];
            Xs[tid * 16 + q] = X[q];
        }
        float xi[6];
        log_se3_dev(X, xi);
#pragma unroll
        for (int q = 0; q < 6; q++) xis[tid * 6 + q] = xi[q];
    }
    __syncthreads();

    // phase 1: input layer; thread owns column tid for 64 rows, store tf32
    {
        float tc = 0.0f;
#pragma unroll 8
        for (int d = 0; d < 64; d++)
            tc += temb[d] * W0[(size_t)(4102 + d) * HDn + tid];
        float w0xi[6];
#pragma unroll
        for (int j = 0; j < 6; j++) w0xi[j] = W0[(size_t)(4096 + j) * HDn + tid];
        for (int r = 0; r < 64; r++) {
            float v = g_H0[(size_t)(brow + r) * HDn + tid] + tc;
#pragma unroll
            for (int j = 0; j < 6; j++) v += xis[r * 6 + j] * w0xi[j];
            ys[r * YS + tid] = f2tf32(gelu_f(v));
        }
    }
    __syncthreads();
    block_ln32(ys, g0, be0, wid, lane);

    // phase 2: 3 hidden layers, 48 chunks, bulk-TMA pingpong
    float acc[2][8][4];
    for (int gc = 0; gc < 48; gc++) {
        int l = gc >> 4, ch = gc & 15, buf = gc & 1;
        if (ch == 0) {
#pragma unroll
            for (int mf = 0; mf < 2; mf++)
#pragma unroll
                for (int nf = 0; nf < 8; nf++)
#pragma unroll
                    for (int q = 0; q < 4; q++) acc[mf][nf][q] = 0.0f;
        }
        __syncthreads();   // all reads of wt[buf^1] (chunk gc-1) done
        if (tid == 0 && gc + 1 < 48) {
            uint32_t mbn = (buf ^ 1) ? mb1 : mb0;
            MBAR_EXPECT(mbn, 16384);
            BULK_G2S(sm_u32(wt + (buf ^ 1) * 4096),
                     (const char*)(g_Wr32 + (size_t)(gc + 1) * 4096), 16384, mbn);
        }
        MBAR_WAIT(buf ? mb1 : mb0, (gc >> 1) & 1);
        const uint32_t* Bh = wt + buf * 4096;
#pragma unroll
        for (int k8 = 0; k8 < 2; k8++) {
            int kcol = ch * 16 + k8 * 8;
            uint32_t a[2][4];
#pragma unroll
            for (int mf = 0; mf < 2; mf++) {
                int r0 = warp_m + mf * 16 + g;
                a[mf][0] = ys[r0 * YS + kcol + t];
                a[mf][1] = ys[(r0 + 8) * YS + kcol + t];
                a[mf][2] = ys[r0 * YS + kcol + t + 4];
                a[mf][3] = ys[(r0 + 8) * YS + kcol + t + 4];
            }
            const uint32_t* Bk = Bh + k8 * 32 * 64;
#pragma unroll
            for (int nf = 0; nf < 8; nf++) {
                uint2 bb = *(const uint2*)&Bk[((warp_n >> 3) + nf) * 64 + lane * 2];
                mma_tf32(acc[0][nf], a[0][0], a[0][1], a[0][2], a[0][3], bb.x, bb.y);
                mma_tf32(acc[1][nf], a[1][0], a[1][1], a[1][2], a[1][3], bb.x, bb.y);
            }
        }
        if (ch == 15) {
            __syncthreads();
#pragma unroll
            for (int nf = 0; nf < 8; nf++) {
                int c0 = warp_n + nf * 8 + 2 * t;
                float bb0 = br[l * HDn + c0], bb1 = br[l * HDn + c0 + 1];
#pragma unroll
                for (int mf = 0; mf < 2; mf++) {
                    int r0 = warp_m + mf * 16 + g;
                    ys[r0 * YS + c0]           = f2tf32(gelu_f(acc[mf][nf][0] + bb0));
                    ys[r0 * YS + c0 + 1]       = f2tf32(gelu_f(acc[mf][nf][1] + bb1));
                    ys[(r0 + 8) * YS + c0]     = f2tf32(gelu_f(acc[mf][nf][2] + bb0));
                    ys[(r0 + 8) * YS + c0 + 1] = f2tf32(gelu_f(acc[mf][nf][3] + bb1));
                }
            }
            __syncthreads();
            block_ln32(ys, gr + l * HDn, ber + l * HDn, wid, lane);
        }
    }
    __syncthreads();

    // phase 3: v = y @ Wout + bout ; X = X @ exp_se3(dt*v)
    for (int rr = 0; rr < 8; rr++) {
        int r = wid * 8 + rr;
        float p[6] = {0, 0, 0, 0, 0, 0};
        for (int c = lane; c < HDn; c += 32) {
            float yv = __uint_as_float(ys[r * YS + c]);
            const float* wp = Wout + c * 6;
#pragma unroll
            for (int j = 0; j < 6; j++) p[j] += yv * wp[j];
        }
#pragma unroll
        for (int j = 0; j < 6; j++)
#pragma unroll
            for (int o = 16; o > 0; o >>= 1)
                p[j] += __shfl_xor_sync(0xffffffffu, p[j], o);
        if (lane == 0) {
            float xi[6];
#pragma unroll
            for (int j = 0; j < 6; j++) xi[j] = dt * (p[j] + bout[j]);
            float M[16];
            exp_se3_dev(xi, M);
            const float* Xo = &Xs[r * 16];
            float Xn[16];
#pragma unroll
            for (int i = 0; i < 4; i++)
#pragma unroll
                for (int j = 0; j < 4; j++) {
                    float s = 0.0f;
#pragma unroll
                    for (int k = 0; k < 4; k++) s += Xo[i * 4 + k] * M[k * 4 + j];
                    Xn[i * 4 + j] = s;
                }
#pragma unroll
            for (int q = 0; q < 16; q++) g_X[(size_t)(brow + r) * 16 + q] = Xn[q];
        }
    }
}

// ---------------- final copy ----------------
__global__ void copy_x_kernel(float* __restrict__ out) {
    int i = blockIdx.x * blockDim.x + threadIdx.x;
    if (i < Bn * 16) out[i] = g_X[i];
}

// ---------------- launch ----------------
extern "C" void kernel_launch(void* const* d_in, const int* in_sizes, int n_in,
                              void* d_out, int out_size) {
    const float* h    = (const float*)d_in[0];
    const float* xi0  = (const float*)d_in[1];
    const float* W0   = (const float*)d_in[2];
    const float* b0   = (const float*)d_in[3];
    const float* g0   = (const float*)d_in[4];
    const float* be0  = (const float*)d_in[5];
    const float* Wr   = (const float*)d_in[6];
    const float* br   = (const float*)d_in[7];
    const float* gr   = (const float*)d_in[8];
    const float* ber  = (const float*)d_in[9];
    const float* Wout = (const float*)d_in[10];
    const float* bout = (const float*)d_in[11];
    const float* gW1  = (const float*)d_in[12];
    const float* gb1  = (const float*)d_in[13];
    const float* gW2  = (const float*)d_in[14];
    const float* gb2  = (const float*)d_in[15];
    const int*   nst  = (const int*)d_in[16];
    float* out = (float*)d_out;

    const int FUSED_SMEM = (4 + 2 * 128 * AP + 2 * 10240 + 128 * 4) * 4;   // ~121 KB
    const int STEP_SMEM  = (4 + 64 * YS + 2 * 4096 + 64 * 16 + 64 * 6 + 64) * 4;  // ~105 KB
    cudaFuncSetAttribute(fused_h_kernel, cudaFuncAttributeMaxDynamicSharedMemorySize, FUSED_SMEM);
    cudaFuncSetAttribute(step_kernel, cudaFuncAttributeMaxDynamicSharedMemorySize, STEP_SMEM);

    prep_wr32<<<384, 256>>>(Wr);
    prep_wc<<<2560, 256>>>(W0, gW1);
    init_kernel<<<Bn / 256, 256>>>(xi0);
    fused_h_kernel<<<Bn / 128, 512, FUSED_SMEM>>>(h, b0, gb1, gW2, gb2, out);
    for (int s = 0; s < 10; s++)
        step_kernel<<<Bn / 64, 256, STEP_SMEM>>>(W0, g0, be0, br, gr, ber,
                                                 Wout, bout, nst, s);
    copy_x_kernel<<<(Bn * 16) / 256, 256>>>(out);
}

// round 13
// speedup vs baseline: 1.8629x; 1.0525x over previous
#include <cuda_runtime.h>
#include <math.h>
#include <stdint.h>

#define Bn   16384
#define HIDn 4096
#define HDn  256
#define YS   260   // ys row stride (words)

// ---------------- scratch ----------------
__device__ float g_H0[Bn * HDn];            // h @ W0[:4096] + b0
__device__ float g_tembW[32 * HDn];         // temb(s) @ W0[4102:4166] per step
// frag-ordered tf32 weights: pair p = ((gc*2 + k8)*32 + nfg)*32 + lane
__device__ uint32_t g_Wr32[48 * 4096];
// fused: pair p = (((tl*4 + cc*2 + k8)*40) + nfg)*32 + lane
__device__ uint32_t g_Wc[128 * 10240];      // W0[:4096,:256] ++ gW1[:, :64]

// ---------------- helpers ----------------
__device__ __forceinline__ float gelu_f(float x) {
    return 0.5f * x * (1.0f + erff(x * 0.70710678118654752f));
}
__device__ __forceinline__ float sigmoid_f(float x) {
    return 1.0f / (1.0f + expf(-x));
}
__device__ __forceinline__ uint32_t f2tf32(float x) {
    uint32_t r;
    asm("cvt.rna.tf32.f32 %0, %1;" : "=r"(r) : "f"(x));
    return r;
}
__device__ __forceinline__ void mma_tf32(float* c, uint32_t a0, uint32_t a1,
                                         uint32_t a2, uint32_t a3,
                                         uint32_t b0, uint32_t b1) {
    asm volatile(
        "mma.sync.aligned.m16n8k8.row.col.f32.tf32.tf32.f32 "
        "{%0,%1,%2,%3}, {%4,%5,%6,%7}, {%8,%9}, {%0,%1,%2,%3};"
        : "+f"(c[0]), "+f"(c[1]), "+f"(c[2]), "+f"(c[3])
        : "r"(a0), "r"(a1), "r"(a2), "r"(a3), "r"(b0), "r"(b1));
}
__device__ __forceinline__ uint32_t sm_u32(const void* p) {
    return (uint32_t)__cvta_generic_to_shared(p);
}
#define MBAR_INIT(addr, cnt) \
    asm volatile("mbarrier.init.shared.b64 [%0], %1;" ::"r"(addr), "r"(cnt) : "memory")
#define MBAR_EXPECT(addr, bytes) \
    asm volatile("mbarrier.arrive.expect_tx.shared.b64 _, [%0], %1;" ::"r"(addr), "r"(bytes) : "memory")
#define BULK_G2S(dst, src, bytes, mbar) \
    asm volatile("cp.async.bulk.shared::cta.global.mbarrier::complete_tx::bytes [%0], [%1], %2, [%3];" \
                 ::"r"(dst), "l"(src), "r"(bytes), "r"(mbar) : "memory")
#define MBAR_WAIT(addr, parity) \
    asm volatile("{\n\t.reg .pred P;\n\tWL%=:\n\tmbarrier.try_wait.parity.shared.b64 P, [%0], %1;\n\t" \
                 "@P bra WD%=;\n\tbra WL%=;\n\tWD%=:\n\t}" ::"r"(addr), "r"(parity) : "memory")

__device__ __forceinline__ void exp_se3_dev(const float* xi, float* X) {
    float wx = xi[0], wy = xi[1], wz = xi[2];
    float vx = xi[3], vy = xi[4], vz = xi[5];
    float th2 = wx * wx + wy * wy + wz * wz + 1e-20f;
    float th  = sqrtf(th2);
    bool small = th < 1e-3f;
    float ths = small ? 1.0f : th;
    float s = sinf(ths), c = cosf(ths);
    float A  = small ? (1.0f - th2 / 6.0f)          : (s / ths);
    float Bc = small ? (0.5f - th2 / 24.0f)         : ((1.0f - c) / (ths * ths));
    float Cc = small ? (1.0f / 6.0f - th2 / 120.0f) : ((ths - s) / (ths * ths * ths));
    float wx2 = wx * wx, wy2 = wy * wy, wz2 = wz * wz;
    float xy = wx * wy, xz = wx * wz, yz = wy * wz;
    float R00 = 1.0f - Bc * (wy2 + wz2), R01 = -A * wz + Bc * xy, R02 =  A * wy + Bc * xz;
    float R10 =  A * wz + Bc * xy, R11 = 1.0f - Bc * (wx2 + wz2), R12 = -A * wx + Bc * yz;
    float R20 = -A * wy + Bc * xz, R21 =  A * wx + Bc * yz, R22 = 1.0f - Bc * (wx2 + wy2);
    float V00 = 1.0f - Cc * (wy2 + wz2), V01 = -Bc * wz + Cc * xy, V02 =  Bc * wy + Cc * xz;
    float V10 =  Bc * wz + Cc * xy, V11 = 1.0f - Cc * (wx2 + wz2), V12 = -Bc * wx + Cc * yz;
    float V20 = -Bc * wy + Cc * xz, V21 =  Bc * wx + Cc * yz, V22 = 1.0f - Cc * (wx2 + wy2);
    X[0] = R00; X[1] = R01; X[2]  = R02; X[3]  = V00 * vx + V01 * vy + V02 * vz;
    X[4] = R10; X[5] = R11; X[6]  = R12; X[7]  = V10 * vx + V11 * vy + V12 * vz;
    X[8] = R20; X[9] = R21; X[10] = R22; X[11] = V20 * vx + V21 * vy + V22 * vz;
    X[12] = 0.0f; X[13] = 0.0f; X[14] = 0.0f; X[15] = 1.0f;
}

__device__ __forceinline__ void log_se3_dev(const float* X, float* xi) {
    float R00 = X[0], R01 = X[1], R02 = X[2],  px = X[3];
    float R10 = X[4], R11 = X[5], R12 = X[6],  py = X[7];
    float R20 = X[8], R21 = X[9], R22 = X[10], pz = X[11];
    float tr = R00 + R11 + R22;
    float cc = fminf(fmaxf((tr - 1.0f) * 0.5f, -1.0f + 1e-7f), 1.0f - 1e-7f);
    float th = acosf(cc);
    bool small = th < 1e-3f;
    float ths = small ? 1.0f : th;
    float sn = sinf(ths), csn = cosf(ths);
    float fac = small ? (0.5f + th * th / 12.0f) : (ths / (2.0f * sn));
    float wx = fac * (R21 - R12);
    float wy = fac * (R02 - R20);
    float wz = fac * (R10 - R01);
    float D = small ? (1.0f / 12.0f)
                    : ((1.0f - ths * sn / (2.0f * (1.0f - csn))) / (ths * ths));
    float wx2 = wx * wx, wy2 = wy * wy, wz2 = wz * wz;
    float xy = wx * wy, xz = wx * wz, yz = wy * wz;
    float V00 = 1.0f - D * (wy2 + wz2), V01 =  0.5f * wz + D * xy, V02 = -0.5f * wy + D * xz;
    float V10 = -0.5f * wz + D * xy, V11 = 1.0f - D * (wx2 + wz2), V12 =  0.5f * wx + D * yz;
    float V20 =  0.5f * wy + D * xz, V21 = -0.5f * wx + D * yz, V22 = 1.0f - D * (wx2 + wy2);
    xi[0] = wx; xi[1] = wy; xi[2] = wz;
    xi[3] = V00 * px + V01 * py + V02 * pz;
    xi[4] = V10 * px + V11 * py + V12 * pz;
    xi[5] = V20 * px + V21 * py + V22 * pz;
}

// ---------------- prep: Wr -> frag-ordered tf32 ----------------
__global__ void prep_wr32(const float* __restrict__ Wr) {
    int p = blockIdx.x * 256 + threadIdx.x;    // 98304 pairs
    int lane = p & 31;
    int rest = p >> 5;
    int nfg = rest & 31;
    int rest2 = rest >> 5;
    int k8 = rest2 & 1, gc = rest2 >> 1;
    int l = gc >> 4, ch = gc & 15;
    int g = lane >> 2, t = lane & 3;
    int w = nfg >> 3, nf = nfg & 7;
    int n = w * 64 + nf * 8 + g;
    int k = ch * 16 + k8 * 8 + t;
    const float* s = Wr + (size_t)l * HDn * HDn + (size_t)k * HDn + n;
    g_Wr32[2 * p]     = f2tf32(s[0]);
    g_Wr32[2 * p + 1] = f2tf32(s[4 * HDn]);
}

// ---------------- prep: [W0 | gW1] -> frag-ordered tf32 ----------------
__global__ void prep_wc(const float* __restrict__ W0, const float* __restrict__ gW1) {
    int p = blockIdx.x * 256 + threadIdx.x;    // 655360 pairs
    int lane = p & 31;
    int rest = p >> 5;
    int nfg = rest % 40;
    int rest2 = rest / 40;
    int k8 = rest2 & 1, cc = (rest2 >> 1) & 1, tl = rest2 >> 2;
    int g = lane >> 2, t = lane & 3;
    int k = tl * 32 + cc * 16 + k8 * 8 + t;
    float s0, s1;
    if (nfg < 32) {
        int w = nfg >> 3, nf = nfg & 7;
        int n = w * 64 + nf * 8 + g;
        s0 = W0[(size_t)k * HDn + n];
        s1 = W0[(size_t)(k + 4) * HDn + n];
    } else {
        int q2 = nfg - 32;
        int w = q2 >> 1, nf2 = q2 & 1;
        int n = w * 16 + nf2 * 8 + g;
        s0 = gW1[(size_t)k * 64 + n];
        s1 = gW1[(size_t)(k + 4) * 64 + n];
    }
    g_Wc[2 * p]     = f2tf32(s0);
    g_Wc[2 * p + 1] = f2tf32(s1);
}

// ---------------- prep: temb(s) @ W0[4102:4166] for each step ----------------
__global__ void prep_temb(const float* __restrict__ W0, const int* __restrict__ nst) {
    int s = blockIdx.x, c = threadIdx.x;
    int ns = *nst;
    if (s >= ns || s >= 32) return;
    float tval = (float)s * (1.0f / (float)ns);
    __shared__ float temb[64];
    if (c < 64) {
        int j = c & 31;
        float freq = expf(-(float)j * (logf(10000.0f) / 31.0f));
        float e = tval * freq;
        temb[c] = (c < 32) ? sinf(e) : cosf(e);
    }
    __syncthreads();
    float tc = 0.0f;
#pragma unroll 8
    for (int d = 0; d < 64; d++)
        tc += temb[d] * W0[(size_t)(4102 + d) * HDn + c];
    g_tembW[s * HDn + c] = tc;
}

// ---------------- fused: H0 = h@W0 + b0  AND  gripper, one h pass ----------------
// grid 128, block 512 (16 warps = 4M x 4N), 128 rows x (256 + 64) cols, k-tile 32
#define AP 36
__global__ void __launch_bounds__(512, 1) fused_h_kernel(
    const float* __restrict__ h, const float* __restrict__ b0,
    const float* __restrict__ gb1, const float* __restrict__ gW2,
    const float* __restrict__ gb2, float* __restrict__ out) {
    extern __shared__ uint32_t sp[];
    uint32_t mb0 = sm_u32(sp), mb1 = mb0 + 8;
    uint32_t* As = sp + 4;                // 2 x 128*36
    uint32_t* Bs = As + 2 * 128 * AP;     // 2 x 10240
    float* sred = (float*)(Bs + 2 * 10240);  // 128 x 4

    int brow = blockIdx.x * 128;
    int tid = threadIdx.x, wid = tid >> 5, lane = tid & 31;
    int g = lane >> 2, t = lane & 3;
    int wm = wid >> 2, wn = wid & 3;
    int warp_m = wm * 32, warp_n = wn * 64;
    int ar = tid >> 2, ac = (tid & 3) * 8;

    float acc[2][8][4];
    float accg[2][2][4];
#pragma unroll
    for (int mf = 0; mf < 2; mf++) {
#pragma unroll
        for (int nf = 0; nf < 8; nf++)
#pragma unroll
            for (int q = 0; q < 4; q++) acc[mf][nf][q] = 0.0f;
#pragma unroll
        for (int nf = 0; nf < 2; nf++)
#pragma unroll
            for (int q = 0; q < 4; q++) accg[mf][nf][q] = 0.0f;
    }

    if (tid == 0) { MBAR_INIT(mb0, 1); MBAR_INIT(mb1, 1); }
    __syncthreads();
    if (tid == 0) {
        MBAR_EXPECT(mb0, 40960);
        BULK_G2S(sm_u32(Bs), (const char*)g_Wc, 40960, mb0);
    }
    float4 a4[2];
    {
        const float* s = h + (size_t)(brow + ar) * HIDn + ac;
        a4[0] = *(const float4*)s; a4[1] = *(const float4*)(s + 4);
    }

    for (int tl = 0; tl < 128; tl++) {
        int buf = tl & 1;
        uint32_t mb = buf ? mb1 : mb0;
        uint32_t mbn = buf ? mb0 : mb1;
        {
            uint32_t* pa = As + buf * (128 * AP) + ar * AP + ac;
            uint4 u0 = make_uint4(f2tf32(a4[0].x), f2tf32(a4[0].y), f2tf32(a4[0].z), f2tf32(a4[0].w));
            uint4 u1 = make_uint4(f2tf32(a4[1].x), f2tf32(a4[1].y), f2tf32(a4[1].z), f2tf32(a4[1].w));
            *(uint4*)pa = u0;
            *(uint4*)(pa + 4) = u1;
        }
        __syncthreads();
        if (tid == 0 && tl + 1 < 128) {
            MBAR_EXPECT(mbn, 40960);
            BULK_G2S(sm_u32(Bs + (buf ^ 1) * 10240),
                     (const char*)(g_Wc + (size_t)(tl + 1) * 10240), 40960, mbn);
        }
        if (tl + 1 < 128) {
            const float* s = h + (size_t)(brow + ar) * HIDn + (tl + 1) * 32 + ac;
            a4[0] = *(const float4*)s; a4[1] = *(const float4*)(s + 4);
        }
        MBAR_WAIT(mb, (tl >> 1) & 1);
        const uint32_t* Asb = As + buf * (128 * AP);
        const uint32_t* Bsb = Bs + buf * 10240;
#pragma unroll
        for (int cc = 0; cc < 2; cc++) {
#pragma unroll
            for (int k8 = 0; k8 < 2; k8++) {
                int kcol = cc * 16 + k8 * 8;
                uint32_t a[2][4];
#pragma unroll
                for (int mf = 0; mf < 2; mf++) {
                    int r0 = (warp_m + mf * 16 + g) * AP + kcol;
                    a[mf][0] = Asb[r0 + t];
                    a[mf][1] = Asb[r0 + 8 * AP + t];
                    a[mf][2] = Asb[r0 + t + 4];
                    a[mf][3] = Asb[r0 + 8 * AP + t + 4];
                }
                const uint32_t* Bk = Bsb + (cc * 2 + k8) * 40 * 64;
#pragma unroll
                for (int nf = 0; nf < 8; nf++) {
                    uint2 bb = *(const uint2*)&Bk[(wn * 8 + nf) * 64 + lane * 2];
                    mma_tf32(acc[0][nf], a[0][0], a[0][1], a[0][2], a[0][3], bb.x, bb.y);
                    mma_tf32(acc[1][nf], a[1][0], a[1][1], a[1][2], a[1][3], bb.x, bb.y);
                }
#pragma unroll
                for (int nf2 = 0; nf2 < 2; nf2++) {
                    uint2 bb = *(const uint2*)&Bk[(32 + wn * 2 + nf2) * 64 + lane * 2];
                    mma_tf32(accg[0][nf2], a[0][0], a[0][1], a[0][2], a[0][3], bb.x, bb.y);
                    mma_tf32(accg[1][nf2], a[1][0], a[1][1], a[1][2], a[1][3], bb.x, bb.y);
                }
            }
        }
    }
#pragma unroll
    for (int mf = 0; mf < 2; mf++) {
        int r0 = brow + warp_m + mf * 16 + g;
#pragma unroll
        for (int nf = 0; nf < 8; nf++) {
            int c0 = warp_n + nf * 8 + 2 * t;
            float bb0 = b0[c0], bb1 = b0[c0 + 1];
            *(float2*)&g_H0[(size_t)r0 * HDn + c0] =
                make_float2(acc[mf][nf][0] + bb0, acc[mf][nf][1] + bb1);
            *(float2*)&g_H0[(size_t)(r0 + 8) * HDn + c0] =
                make_float2(acc[mf][nf][2] + bb0, acc[mf][nf][3] + bb1);
        }
    }
    float pr[4] = {0, 0, 0, 0};
#pragma unroll
    for (int nf2 = 0; nf2 < 2; nf2++) {
        int c0 = wn * 16 + nf2 * 8 + 2 * t;
        float bb0 = gb1[c0], bb1 = gb1[c0 + 1];
        float w0 = gW2[c0], w1 = gW2[c0 + 1];
#pragma unroll
        for (int mf = 0; mf < 2; mf++) {
            pr[mf * 2 + 0] += gelu_f(accg[mf][nf2][0] + bb0) * w0
                            + gelu_f(accg[mf][nf2][1] + bb1) * w1;
            pr[mf * 2 + 1] += gelu_f(accg[mf][nf2][2] + bb0) * w0
                            + gelu_f(accg[mf][nf2][3] + bb1) * w1;
        }
    }
#pragma unroll
    for (int j = 0; j < 4; j++) {
        pr[j] += __shfl_xor_sync(0xffffffffu, pr[j], 1);
        pr[j] += __shfl_xor_sync(0xffffffffu, pr[j], 2);
    }
    __syncthreads();
    if (t == 0) {
        sred[(warp_m + g) * 4 + wn]      = pr[0];
        sred[(warp_m + g + 8) * 4 + wn]  = pr[1];
        sred[(warp_m + 16 + g) * 4 + wn] = pr[2];
        sred[(warp_m + 24 + g) * 4 + wn] = pr[3];
    }
    __syncthreads();
    if (tid < 128) {
        float s = sred[tid * 4] + sred[tid * 4 + 1] + sred[tid * 4 + 2] + sred[tid * 4 + 3];
        out[(size_t)Bn * 16 + brow + tid] = sigmoid_f(s + gb2[0]);
    }
}

// ---------------- layernorm on tf32-bit ys ----------------
__device__ __forceinline__ void block_ln32(uint32_t* ys, const float* __restrict__ g_,
                                           const float* __restrict__ be_, int wid, int lane) {
    float gv[8], bv[8];
#pragma unroll
    for (int j = 0; j < 8; j++) { gv[j] = g_[lane + j * 32]; bv[j] = be_[lane + j * 32]; }
#pragma unroll
    for (int rr = 0; rr < 8; rr++) {
        int r = wid * 8 + rr;
        float v[8]; float s = 0.0f, s2 = 0.0f;
#pragma unroll
        for (int j = 0; j < 8; j++) {
            v[j] = __uint_as_float(ys[r * YS + lane + j * 32]);
            s += v[j]; s2 += v[j] * v[j];
        }
#pragma unroll
        for (int o = 16; o > 0; o >>= 1) {
            s  += __shfl_xor_sync(0xffffffffu, s,  o);
            s2 += __shfl_xor_sync(0xffffffffu, s2, o);
        }
        float m   = s * (1.0f / HDn);
        float var = s2 * (1.0f / HDn) - m * m;
        float rv  = rsqrtf(var + 1e-5f);
#pragma unroll
        for (int j = 0; j < 8; j++)
            ys[r * YS + lane + j * 32] = f2tf32((v[j] - m) * rv * gv[j] + bv[j]);
    }
}

// ---------------- persistent ODE kernel: all steps in one launch ----------------
// 64 rows/block, 256 threads, 8 warps (2M x 4N), warp tile 32x64
// Weights streamed per-warp via LDG.64 register pipeline; no intra-layer barriers.
__global__ void __launch_bounds__(256, 2) ode_kernel(
    const float* __restrict__ xi0, const float* __restrict__ W0,
    const float* __restrict__ g0,  const float* __restrict__ be0,
    const float* __restrict__ br,  const float* __restrict__ gr,
    const float* __restrict__ ber, const float* __restrict__ Wout,
    const float* __restrict__ bout, const int* __restrict__ n_steps_p,
    float* __restrict__ out) {
    extern __shared__ uint32_t sp[];
    uint32_t* ys = sp;                      // 64*260 (tf32 bits)
    float* Xs   = (float*)(ys + 64 * YS);   // 64*16
    float* xis  = Xs + 64 * 16;             // 64*6

    int ns = *n_steps_p;
    float dt = 1.0f / (float)ns;
    int tid = threadIdx.x;
    int brow = blockIdx.x * 64;
    int wid = tid >> 5, lane = tid & 31;
    int g = lane >> 2, t = lane & 3;
    int warp_m = (wid >> 2) * 32, warp_n = (wid & 3) * 64;
    int wn8 = (wid & 3) * 8;

    // per-warp weight base (frag-ordered): chunk gc at +gc*4096, k8 at +2048
    const uint32_t* wbase = g_Wr32 + (size_t)wn8 * 64 + lane * 2;

    // hoisted xi-weights (constant across steps)
    float w0xi[6];
#pragma unroll
    for (int j = 0; j < 6; j++) w0xi[j] = W0[(size_t)(4096 + j) * HDn + tid];

    // register weight pipeline: preload chunk 0, k8=0
    uint2 br0[8], br1[8];
#pragma unroll
    for (int nf = 0; nf < 8; nf++) br0[nf] = *(const uint2*)(wbase + nf * 64);

    // X0 = exp_se3(0.1 * xi0)
    if (tid < 64) {
        float xi[6];
#pragma unroll
        for (int j = 0; j < 6; j++) xi[j] = 0.1f * xi0[(brow + tid) * 6 + j];
        exp_se3_dev(xi, &Xs[tid * 16]);
    }
    __syncthreads();

    for (int s = 0; s < ns; s++) {
        // phase 0: log_se3 of current state
        if (tid < 64) {
            float xi[6];
            log_se3_dev(&Xs[tid * 16], xi);
#pragma unroll
            for (int q = 0; q < 6; q++) xis[tid * 6 + q] = xi[q];
        }
        __syncthreads();

        // phase 1: input layer (column tid over 64 rows)
        {
            float tc;
            if (s < 32) tc = g_tembW[s * HDn + tid];
            else {
                tc = 0.0f;
                float tval = (float)s * dt;
#pragma unroll 8
                for (int d = 0; d < 64; d++) {
                    int j = d & 31;
                    float freq = expf(-(float)j * (logf(10000.0f) / 31.0f));
                    float e = tval * freq;
                    float tb = (d < 32) ? sinf(e) : cosf(e);
                    tc += tb * W0[(size_t)(4102 + d) * HDn + tid];
                }
            }
            for (int r = 0; r < 64; r++) {
                float v = g_H0[(size_t)(brow + r) * HDn + tid] + tc;
#pragma unroll
                for (int j = 0; j < 6; j++) v += xis[r * 6 + j] * w0xi[j];
                ys[r * YS + tid] = f2tf32(gelu_f(v));
            }
        }
        __syncthreads();
        block_ln32(ys, g0, be0, wid, lane);
        __syncthreads();

        // phase 2: 3 hidden layers, 48 chunks, register-pipelined LDG weights,
        // no block barriers inside a layer
        float acc[2][8][4];
        for (int gc = 0; gc < 48; gc++) {
            int ch = gc & 15, l = gc >> 4;
            if (ch == 0) {
#pragma unroll
                for (int mf = 0; mf < 2; mf++)
#pragma unroll
                    for (int nf = 0; nf < 8; nf++)
#pragma unroll
                        for (int q = 0; q < 4; q++) acc[mf][nf][q] = 0.0f;
            }
            const uint32_t* wb = wbase + (size_t)gc * 4096;
            // prefetch k8=1 of this chunk
#pragma unroll
            for (int nf = 0; nf < 8; nf++) br1[nf] = *(const uint2*)(wb + 2048 + nf * 64);
            // k8 = 0 MMAs (br0 preloaded)
            {
                int kcol = ch * 16;
                uint32_t a[2][4];
#pragma unroll
                for (int mf = 0; mf < 2; mf++) {
                    int r0 = warp_m + mf * 16 + g;
                    a[mf][0] = ys[r0 * YS + kcol + t];
                    a[mf][1] = ys[(r0 + 8) * YS + kcol + t];
                    a[mf][2] = ys[r0 * YS + kcol + t + 4];
                    a[mf][3] = ys[(r0 + 8) * YS + kcol + t + 4];
                }
#pragma unroll
                for (int nf = 0; nf < 8; nf++) {
                    mma_tf32(acc[0][nf], a[0][0], a[0][1], a[0][2], a[0][3], br0[nf].x, br0[nf].y);
                    mma_tf32(acc[1][nf], a[1][0], a[1][1], a[1][2], a[1][3], br0[nf].x, br0[nf].y);
                }
            }
            // prefetch k8=0 of next chunk (wraps to chunk 0 for next step)
            {
                int gn = (gc + 1 < 48) ? gc + 1 : 0;
                const uint32_t* wn_ = wbase + (size_t)gn * 4096;
#pragma unroll
                for (int nf = 0; nf < 8; nf++) br0[nf] = *(const uint2*)(wn_ + nf * 64);
            }
            // k8 = 1 MMAs
            {
                int kcol = ch * 16 + 8;
                uint32_t a[2][4];
#pragma unroll
                for (int mf = 0; mf < 2; mf++) {
                    int r0 = warp_m + mf * 16 + g;
                    a[mf][0] = ys[r0 * YS + kcol + t];
                    a[mf][1] = ys[(r0 + 8) * YS + kcol + t];
                    a[mf][2] = ys[r0 * YS + kcol + t + 4];
                    a[mf][3] = ys[(r0 + 8) * YS + kcol + t + 4];
                }
#pragma unroll
                for (int nf = 0; nf < 8; nf++) {
                    mma_tf32(acc[0][nf], a[0][0], a[0][1], a[0][2], a[0][3], br1[nf].x, br1[nf].y);
                    mma_tf32(acc[1][nf], a[1][0], a[1][1], a[1][2], a[1][3], br1[nf].x, br1[nf].y);
                }
            }
            if (ch == 15) {
                __syncthreads();   // all warps done reading ys for this layer
#pragma unroll
                for (int nf = 0; nf < 8; nf++) {
                    int c0 = warp_n + nf * 8 + 2 * t;
                    float bb0 = br[l * HDn + c0], bb1 = br[l * HDn + c0 + 1];
#pragma unroll
                    for (int mf = 0; mf < 2; mf++) {
                        int r0 = warp_m + mf * 16 + g;
                        ys[r0 * YS + c0]           = f2tf32(gelu_f(acc[mf][nf][0] + bb0));
                        ys[r0 * YS + c0 + 1]       = f2tf32(gelu_f(acc[mf][nf][1] + bb1));
                        ys[(r0 + 8) * YS + c0]     = f2tf32(gelu_f(acc[mf][nf][2] + bb0));
                        ys[(r0 + 8) * YS + c0 + 1] = f2tf32(gelu_f(acc[mf][nf][3] + bb1));
                    }
                }
                __syncthreads();
                block_ln32(ys, gr + l * HDn, ber + l * HDn, wid, lane);
                __syncthreads();
            }
        }

        // phase 3: v = y @ Wout + bout ; X = X @ exp_se3(dt*v)
        for (int rr = 0; rr < 8; rr++) {
            int r = wid * 8 + rr;
            float p[6] = {0, 0, 0, 0, 0, 0};
            for (int c = lane; c < HDn; c += 32) {
                float yv = __uint_as_float(ys[r * YS + c]);
                const float* wp = Wout + c * 6;
#pragma unroll
                for (int j = 0; j < 6; j++) p[j] += yv * wp[j];
            }
#pragma unroll
            for (int j = 0; j < 6; j++)
#pragma unroll
                for (int o = 16; o > 0; o >>= 1)
                    p[j] += __shfl_xor_sync(0xffffffffu, p[j], o);
            if (lane == 0) {
                float xi[6];
#pragma unroll
                for (int j = 0; j < 6; j++) xi[j] = dt * (p[j] + bout[j]);
                float M[16];
                exp_se3_dev(xi, M);
                float Xo[16];
#pragma unroll
                for (int q = 0; q < 16; q++) Xo[q] = Xs[r * 16 + q];
#pragma unroll
                for (int i = 0; i < 4; i++)
#pragma unroll
                    for (int j = 0; j < 4; j++) {
                        float sm = 0.0f;
#pragma unroll
                        for (int k = 0; k < 4; k++) sm += Xo[i * 4 + k] * M[k * 4 + j];
                        Xs[r * 16 + i * 4 + j] = sm;
                    }
            }
        }
        __syncthreads();   // Xs/ys stable for next step
    }

    // write final X to output
    {
        int row = tid >> 2, q4 = (tid & 3) * 4;
        float4 v = *(float4*)&Xs[row * 16 + q4];
        *(float4*)&out[(size_t)(brow + row) * 16 + q4] = v;
    }
}

// ---------------- launch ----------------
extern "C" void kernel_launch(void* const* d_in, const int* in_sizes, int n_in,
                              void* d_out, int out_size) {
    const float* h    = (const float*)d_in[0];
    const float* xi0  = (const float*)d_in[1];
    const float* W0   = (const float*)d_in[2];
    const float* b0   = (const float*)d_in[3];
    const float* g0   = (const float*)d_in[4];
    const float* be0  = (const float*)d_in[5];
    const float* Wr   = (const float*)d_in[6];
    const float* br   = (const float*)d_in[7];
    const float* gr   = (const float*)d_in[8];
    const float* ber  = (const float*)d_in[9];
    const float* Wout = (const float*)d_in[10];
    const float* bout = (const float*)d_in[11];
    const float* gW1  = (const float*)d_in[12];
    const float* gb1  = (const float*)d_in[13];
    const float* gW2  = (const float*)d_in[14];
    const float* gb2  = (const float*)d_in[15];
    const int*   nst  = (const int*)d_in[16];
    float* out = (float*)d_out;

    const int FUSED_SMEM = (4 + 2 * 128 * AP + 2 * 10240 + 128 * 4) * 4;   // ~121 KB
    const int ODE_SMEM   = (64 * YS + 64 * 16 + 64 * 6) * 4;               // ~71 KB
    cudaFuncSetAttribute(fused_h_kernel, cudaFuncAttributeMaxDynamicSharedMemorySize, FUSED_SMEM);
    cudaFuncSetAttribute(ode_kernel, cudaFuncAttributeMaxDynamicSharedMemorySize, ODE_SMEM);

    prep_wr32<<<384, 256>>>(Wr);
    prep_wc<<<2560, 256>>>(W0, gW1);
    prep_temb<<<32, 256>>>(W0, nst);
    fused_h_kernel<<<Bn / 128, 512, FUSED_SMEM>>>(h, b0, gb1, gW2, gb2, out);
    ode_kernel<<<Bn / 64, 256, ODE_SMEM>>>(xi0, W0, g0, be0, br, gr, ber,
                                           Wout, bout, nst, out);
}

// round 14
// speedup vs baseline: 1.8669x; 1.0022x over previous
#include <cuda_runtime.h>
#include <math.h>
#include <stdint.h>

#define Bn   16384
#define HIDn 4096
#define HDn  256
#define YS   260   // ys row stride (words)

// ---------------- scratch ----------------
__device__ float g_H0[Bn * HDn];            // h @ W0[:4096] + b0
__device__ float g_tembW[32 * HDn];         // temb(s) @ W0[4102:4166] per step
// frag-ordered tf32 weights: pair p = ((gc*2 + k8)*32 + nfg)*32 + lane
__device__ uint32_t g_Wr32[48 * 4096];
// fused: pair p = (((tl*4 + cc*2 + k8)*40) + nfg)*32 + lane
__device__ uint32_t g_Wc[128 * 10240];      // W0[:4096,:256] ++ gW1[:, :64]

// ---------------- helpers ----------------
__device__ __forceinline__ float gelu_f(float x) {
    return 0.5f * x * (1.0f + erff(x * 0.70710678118654752f));
}
__device__ __forceinline__ float sigmoid_f(float x) {
    return 1.0f / (1.0f + expf(-x));
}
__device__ __forceinline__ uint32_t f2tf32(float x) {
    uint32_t r;
    asm("cvt.rna.tf32.f32 %0, %1;" : "=r"(r) : "f"(x));
    return r;
}
__device__ __forceinline__ void mma_tf32(float* c, uint32_t a0, uint32_t a1,
                                         uint32_t a2, uint32_t a3,
                                         uint32_t b0, uint32_t b1) {
    asm volatile(
        "mma.sync.aligned.m16n8k8.row.col.f32.tf32.tf32.f32 "
        "{%0,%1,%2,%3}, {%4,%5,%6,%7}, {%8,%9}, {%0,%1,%2,%3};"
        : "+f"(c[0]), "+f"(c[1]), "+f"(c[2]), "+f"(c[3])
        : "r"(a0), "r"(a1), "r"(a2), "r"(a3), "r"(b0), "r"(b1));
}
__device__ __forceinline__ uint32_t sm_u32(const void* p) {
    return (uint32_t)__cvta_generic_to_shared(p);
}
#define MBAR_INIT(addr, cnt) \
    asm volatile("mbarrier.init.shared.b64 [%0], %1;" ::"r"(addr), "r"(cnt) : "memory")
#define MBAR_EXPECT(addr, bytes) \
    asm volatile("mbarrier.arrive.expect_tx.shared.b64 _, [%0], %1;" ::"r"(addr), "r"(bytes) : "memory")
#define BULK_G2S(dst, src, bytes, mbar) \
    asm volatile("cp.async.bulk.shared::cta.global.mbarrier::complete_tx::bytes [%0], [%1], %2, [%3];" \
                 ::"r"(dst), "l"(src), "r"(bytes), "r"(mbar) : "memory")
#define MBAR_WAIT(addr, parity) \
    asm volatile("{\n\t.reg .pred P;\n\tWL%=:\n\tmbarrier.try_wait.parity.shared.b64 P, [%0], %1;\n\t" \
                 "@P bra WD%=;\n\tbra WL%=;\n\tWD%=:\n\t}" ::"r"(addr), "r"(parity) : "memory")

__device__ __forceinline__ void exp_se3_dev(const float* xi, float* X) {
    float wx = xi[0], wy = xi[1], wz = xi[2];
    float vx = xi[3], vy = xi[4], vz = xi[5];
    float th2 = wx * wx + wy * wy + wz * wz + 1e-20f;
    float th  = sqrtf(th2);
    bool small = th < 1e-3f;
    float ths = small ? 1.0f : th;
    float s = sinf(ths), c = cosf(ths);
    float A  = small ? (1.0f - th2 / 6.0f)          : (s / ths);
    float Bc = small ? (0.5f - th2 / 24.0f)         : ((1.0f - c) / (ths * ths));
    float Cc = small ? (1.0f / 6.0f - th2 / 120.0f) : ((ths - s) / (ths * ths * ths));
    float wx2 = wx * wx, wy2 = wy * wy, wz2 = wz * wz;
    float xy = wx * wy, xz = wx * wz, yz = wy * wz;
    float R00 = 1.0f - Bc * (wy2 + wz2), R01 = -A * wz + Bc * xy, R02 =  A * wy + Bc * xz;
    float R10 =  A * wz + Bc * xy, R11 = 1.0f - Bc * (wx2 + wz2), R12 = -A * wx + Bc * yz;
    float R20 = -A * wy + Bc * xz, R21 =  A * wx + Bc * yz, R22 = 1.0f - Bc * (wx2 + wy2);
    float V00 = 1.0f - Cc * (wy2 + wz2), V01 = -Bc * wz + Cc * xy, V02 =  Bc * wy + Cc * xz;
    float V10 =  Bc * wz + Cc * xy, V11 = 1.0f - Cc * (wx2 + wz2), V12 = -Bc * wx + Cc * yz;
    float V20 = -Bc * wy + Cc * xz, V21 =  Bc * wx + Cc * yz, V22 = 1.0f - Cc * (wx2 + wy2);
    X[0] = R00; X[1] = R01; X[2]  = R02; X[3]  = V00 * vx + V01 * vy + V02 * vz;
    X[4] = R10; X[5] = R11; X[6]  = R12; X[7]  = V10 * vx + V11 * vy + V12 * vz;
    X[8] = R20; X[9] = R21; X[10] = R22; X[11] = V20 * vx + V21 * vy + V22 * vz;
    X[12] = 0.0f; X[13] = 0.0f; X[14] = 0.0f; X[15] = 1.0f;
}

__device__ __forceinline__ void log_se3_dev(const float* X, float* xi) {
    float R00 = X[0], R01 = X[1], R02 = X[2],  px = X[3];
    float R10 = X[4], R11 = X[5], R12 = X[6],  py = X[7];
    float R20 = X[8], R21 = X[9], R22 = X[10], pz = X[11];
    float tr = R00 + R11 + R22;
    float cc = fminf(fmaxf((tr - 1.0f) * 0.5f, -1.0f + 1e-7f), 1.0f - 1e-7f);
    float th = acosf(cc);
    bool small = th < 1e-3f;
    float ths = small ? 1.0f : th;
    float sn = sinf(ths), csn = cosf(ths);
    float fac = small ? (0.5f + th * th / 12.0f) : (ths / (2.0f * sn));
    float wx = fac * (R21 - R12);
    float wy = fac * (R02 - R20);
    float wz = fac * (R10 - R01);
    float D = small ? (1.0f / 12.0f)
                    : ((1.0f - ths * sn / (2.0f * (1.0f - csn))) / (ths * ths));
    float wx2 = wx * wx, wy2 = wy * wy, wz2 = wz * wz;
    float xy = wx * wy, xz = wx * wz, yz = wy * wz;
    float V00 = 1.0f - D * (wy2 + wz2), V01 =  0.5f * wz + D * xy, V02 = -0.5f * wy + D * xz;
    float V10 = -0.5f * wz + D * xy, V11 = 1.0f - D * (wx2 + wz2), V12 =  0.5f * wx + D * yz;
    float V20 =  0.5f * wy + D * xz, V21 = -0.5f * wx + D * yz, V22 = 1.0f - D * (wx2 + wy2);
    xi[0] = wx; xi[1] = wy; xi[2] = wz;
    xi[3] = V00 * px + V01 * py + V02 * pz;
    xi[4] = V10 * px + V11 * py + V12 * pz;
    xi[5] = V20 * px + V21 * py + V22 * pz;
}

// ---------------- prep: Wr -> frag-ordered tf32 ----------------
__global__ void prep_wr32(const float* __restrict__ Wr) {
    int p = blockIdx.x * 256 + threadIdx.x;    // 98304 pairs
    int lane = p & 31;
    int rest = p >> 5;
    int nfg = rest & 31;
    int rest2 = rest >> 5;
    int k8 = rest2 & 1, gc = rest2 >> 1;
    int l = gc >> 4, ch = gc & 15;
    int g = lane >> 2, t = lane & 3;
    int w = nfg >> 3, nf = nfg & 7;
    int n = w * 64 + nf * 8 + g;
    int k = ch * 16 + k8 * 8 + t;
    const float* s = Wr + (size_t)l * HDn * HDn + (size_t)k * HDn + n;
    g_Wr32[2 * p]     = f2tf32(s[0]);
    g_Wr32[2 * p + 1] = f2tf32(s[4 * HDn]);
}

// ---------------- prep: [W0 | gW1] -> frag-ordered tf32 ----------------
__global__ void prep_wc(const float* __restrict__ W0, const float* __restrict__ gW1) {
    int p = blockIdx.x * 256 + threadIdx.x;    // 655360 pairs
    int lane = p & 31;
    int rest = p >> 5;
    int nfg = rest % 40;
    int rest2 = rest / 40;
    int k8 = rest2 & 1, cc = (rest2 >> 1) & 1, tl = rest2 >> 2;
    int g = lane >> 2, t = lane & 3;
    int k = tl * 32 + cc * 16 + k8 * 8 + t;
    float s0, s1;
    if (nfg < 32) {
        int w = nfg >> 3, nf = nfg & 7;
        int n = w * 64 + nf * 8 + g;
        s0 = W0[(size_t)k * HDn + n];
        s1 = W0[(size_t)(k + 4) * HDn + n];
    } else {
        int q2 = nfg - 32;
        int w = q2 >> 1, nf2 = q2 & 1;
        int n = w * 16 + nf2 * 8 + g;
        s0 = gW1[(size_t)k * 64 + n];
        s1 = gW1[(size_t)(k + 4) * 64 + n];
    }
    g_Wc[2 * p]     = f2tf32(s0);
    g_Wc[2 * p + 1] = f2tf32(s1);
}

// ---------------- prep: temb(s) @ W0[4102:4166] for each step ----------------
__global__ void prep_temb(const float* __restrict__ W0, const int* __restrict__ nst) {
    int s = blockIdx.x, c = threadIdx.x;
    int ns = *nst;
    if (s >= ns || s >= 32) return;
    float tval = (float)s * (1.0f / (float)ns);
    __shared__ float temb[64];
    if (c < 64) {
        int j = c & 31;
        float freq = expf(-(float)j * (logf(10000.0f) / 31.0f));
        float e = tval * freq;
        temb[c] = (c < 32) ? sinf(e) : cosf(e);
    }
    __syncthreads();
    float tc = 0.0f;
#pragma unroll 8
    for (int d = 0; d < 64; d++)
        tc += temb[d] * W0[(size_t)(4102 + d) * HDn + c];
    g_tembW[s * HDn + c] = tc;
}

// ---------------- fused: H0 = h@W0 + b0  AND  gripper, one h pass ----------------
// grid 128, block 512 (16 warps = 4M x 4N), 128 rows x (256 + 64) cols, k-tile 32
#define AP 36
__global__ void __launch_bounds__(512, 1) fused_h_kernel(
    const float* __restrict__ h, const float* __restrict__ b0,
    const float* __restrict__ gb1, const float* __restrict__ gW2,
    const float* __restrict__ gb2, float* __restrict__ out) {
    extern __shared__ uint32_t sp[];
    uint32_t mb0 = sm_u32(sp), mb1 = mb0 + 8;
    uint32_t* As = sp + 4;                // 2 x 128*36
    uint32_t* Bs = As + 2 * 128 * AP;     // 2 x 10240
    float* sred = (float*)(Bs + 2 * 10240);  // 128 x 4

    int brow = blockIdx.x * 128;
    int tid = threadIdx.x, wid = tid >> 5, lane = tid & 31;
    int g = lane >> 2, t = lane & 3;
    int wm = wid >> 2, wn = wid & 3;
    int warp_m = wm * 32, warp_n = wn * 64;
    int ar = tid >> 2, ac = (tid & 3) * 8;

    float acc[2][8][4];
    float accg[2][2][4];
#pragma unroll
    for (int mf = 0; mf < 2; mf++) {
#pragma unroll
        for (int nf = 0; nf < 8; nf++)
#pragma unroll
            for (int q = 0; q < 4; q++) acc[mf][nf][q] = 0.0f;
#pragma unroll
        for (int nf = 0; nf < 2; nf++)
#pragma unroll
            for (int q = 0; q < 4; q++) accg[mf][nf][q] = 0.0f;
    }

    if (tid == 0) { MBAR_INIT(mb0, 1); MBAR_INIT(mb1, 1); }
    __syncthreads();
    if (tid == 0) {
        MBAR_EXPECT(mb0, 40960);
        BULK_G2S(sm_u32(Bs), (const char*)g_Wc, 40960, mb0);
    }
    float4 a4[2];
    {
        const float* s = h + (size_t)(brow + ar) * HIDn + ac;
        a4[0] = *(const float4*)s; a4[1] = *(const float4*)(s + 4);
    }

    for (int tl = 0; tl < 128; tl++) {
        int buf = tl & 1;
        uint32_t mb = buf ? mb1 : mb0;
        uint32_t mbn = buf ? mb0 : mb1;
        {
            uint32_t* pa = As + buf * (128 * AP) + ar * AP + ac;
            uint4 u0 = make_uint4(f2tf32(a4[0].x), f2tf32(a4[0].y), f2tf32(a4[0].z), f2tf32(a4[0].w));
            uint4 u1 = make_uint4(f2tf32(a4[1].x), f2tf32(a4[1].y), f2tf32(a4[1].z), f2tf32(a4[1].w));
            *(uint4*)pa = u0;
            *(uint4*)(pa + 4) = u1;
        }
        __syncthreads();
        if (tid == 0 && tl + 1 < 128) {
            MBAR_EXPECT(mbn, 40960);
            BULK_G2S(sm_u32(Bs + (buf ^ 1) * 10240),
                     (const char*)(g_Wc + (size_t)(tl + 1) * 10240), 40960, mbn);
        }
        if (tl + 1 < 128) {
            const float* s = h + (size_t)(brow + ar) * HIDn + (tl + 1) * 32 + ac;
            a4[0] = *(const float4*)s; a4[1] = *(const float4*)(s + 4);
        }
        MBAR_WAIT(mb, (tl >> 1) & 1);
        const uint32_t* Asb = As + buf * (128 * AP);
        const uint32_t* Bsb = Bs + buf * 10240;
#pragma unroll
        for (int cc = 0; cc < 2; cc++) {
#pragma unroll
            for (int k8 = 0; k8 < 2; k8++) {
                int kcol = cc * 16 + k8 * 8;
                uint32_t a[2][4];
#pragma unroll
                for (int mf = 0; mf < 2; mf++) {
                    int r0 = (warp_m + mf * 16 + g) * AP + kcol;
                    a[mf][0] = Asb[r0 + t];
                    a[mf][1] = Asb[r0 + 8 * AP + t];
                    a[mf][2] = Asb[r0 + t + 4];
                    a[mf][3] = Asb[r0 + 8 * AP + t + 4];
                }
                const uint32_t* Bk = Bsb + (cc * 2 + k8) * 40 * 64;
#pragma unroll
                for (int nf = 0; nf < 8; nf++) {
                    uint2 bb = *(const uint2*)&Bk[(wn * 8 + nf) * 64 + lane * 2];
                    mma_tf32(acc[0][nf], a[0][0], a[0][1], a[0][2], a[0][3], bb.x, bb.y);
                    mma_tf32(acc[1][nf], a[1][0], a[1][1], a[1][2], a[1][3], bb.x, bb.y);
                }
#pragma unroll
                for (int nf2 = 0; nf2 < 2; nf2++) {
                    uint2 bb = *(const uint2*)&Bk[(32 + wn * 2 + nf2) * 64 + lane * 2];
                    mma_tf32(accg[0][nf2], a[0][0], a[0][1], a[0][2], a[0][3], bb.x, bb.y);
                    mma_tf32(accg[1][nf2], a[1][0], a[1][1], a[1][2], a[1][3], bb.x, bb.y);
                }
            }
        }
    }
#pragma unroll
    for (int mf = 0; mf < 2; mf++) {
        int r0 = brow + warp_m + mf * 16 + g;
#pragma unroll
        for (int nf = 0; nf < 8; nf++) {
            int c0 = warp_n + nf * 8 + 2 * t;
            float bb0 = b0[c0], bb1 = b0[c0 + 1];
            *(float2*)&g_H0[(size_t)r0 * HDn + c0] =
                make_float2(acc[mf][nf][0] + bb0, acc[mf][nf][1] + bb1);
            *(float2*)&g_H0[(size_t)(r0 + 8) * HDn + c0] =
                make_float2(acc[mf][nf][2] + bb0, acc[mf][nf][3] + bb1);
        }
    }
    float pr[4] = {0, 0, 0, 0};
#pragma unroll
    for (int nf2 = 0; nf2 < 2; nf2++) {
        int c0 = wn * 16 + nf2 * 8 + 2 * t;
        float bb0 = gb1[c0], bb1 = gb1[c0 + 1];
        float w0 = gW2[c0], w1 = gW2[c0 + 1];
#pragma unroll
        for (int mf = 0; mf < 2; mf++) {
            pr[mf * 2 + 0] += gelu_f(accg[mf][nf2][0] + bb0) * w0
                            + gelu_f(accg[mf][nf2][1] + bb1) * w1;
            pr[mf * 2 + 1] += gelu_f(accg[mf][nf2][2] + bb0) * w0
                            + gelu_f(accg[mf][nf2][3] + bb1) * w1;
        }
    }
#pragma unroll
    for (int j = 0; j < 4; j++) {
        pr[j] += __shfl_xor_sync(0xffffffffu, pr[j], 1);
        pr[j] += __shfl_xor_sync(0xffffffffu, pr[j], 2);
    }
    __syncthreads();
    if (t == 0) {
        sred[(warp_m + g) * 4 + wn]      = pr[0];
        sred[(warp_m + g + 8) * 4 + wn]  = pr[1];
        sred[(warp_m + 16 + g) * 4 + wn] = pr[2];
        sred[(warp_m + 24 + g) * 4 + wn] = pr[3];
    }
    __syncthreads();
    if (tid < 128) {
        float s = sred[tid * 4] + sred[tid * 4 + 1] + sred[tid * 4 + 2] + sred[tid * 4 + 3];
        out[(size_t)Bn * 16 + brow + tid] = sigmoid_f(s + gb2[0]);
    }
}

// ---------------- layernorm on tf32-bit ys ----------------
__device__ __forceinline__ void block_ln32(uint32_t* ys, const float* __restrict__ g_,
                                           const float* __restrict__ be_, int wid, int lane) {
    float gv[8], bv[8];
#pragma unroll
    for (int j = 0; j < 8; j++) { gv[j] = g_[lane + j * 32]; bv[j] = be_[lane + j * 32]; }
#pragma unroll
    for (int rr = 0; rr < 8; rr++) {
        int r = wid * 8 + rr;
        float v[8]; float s = 0.0f, s2 = 0.0f;
#pragma unroll
        for (int j = 0; j < 8; j++) {
            v[j] = __uint_as_float(ys[r * YS + lane + j * 32]);
            s += v[j]; s2 += v[j] * v[j];
        }
#pragma unroll
        for (int o = 16; o > 0; o >>= 1) {
            s  += __shfl_xor_sync(0xffffffffu, s,  o);
            s2 += __shfl_xor_sync(0xffffffffu, s2, o);
        }
        float m   = s * (1.0f / HDn);
        float var = s2 * (1.0f / HDn) - m * m;
        float rv  = rsqrtf(var + 1e-5f);
#pragma unroll
        for (int j = 0; j < 8; j++)
            ys[r * YS + lane + j * 32] = f2tf32((v[j] - m) * rv * gv[j] + bv[j]);
    }
}

// ---------------- persistent ODE kernel: all steps in one launch ----------------
// 64 rows/block, 256 threads, 8 warps (2M x 4N), warp tile 32x64
// Weights streamed per-warp via LDG.64 register pipeline; no intra-layer barriers.
__global__ void __launch_bounds__(256, 2) ode_kernel(
    const float* __restrict__ xi0, const float* __restrict__ W0,
    const float* __restrict__ g0,  const float* __restrict__ be0,
    const float* __restrict__ br,  const float* __restrict__ gr,
    const float* __restrict__ ber, const float* __restrict__ Wout,
    const float* __restrict__ bout, const int* __restrict__ n_steps_p,
    float* __restrict__ out) {
    extern __shared__ uint32_t sp[];
    uint32_t* ys = sp;                      // 64*260 (tf32 bits)
    float* Xs   = (float*)(ys + 64 * YS);   // 64*16
    float* xis  = Xs + 64 * 16;             // 64*6

    int ns = *n_steps_p;
    float dt = 1.0f / (float)ns;
    int tid = threadIdx.x;
    int brow = blockIdx.x * 64;
    int wid = tid >> 5, lane = tid & 31;
    int g = lane >> 2, t = lane & 3;
    int warp_m = (wid >> 2) * 32, warp_n = (wid & 3) * 64;
    int wn8 = (wid & 3) * 8;

    // per-warp weight base (frag-ordered): chunk gc at +gc*4096, k8 at +2048
    const uint32_t* wbase = g_Wr32 + (size_t)wn8 * 64 + lane * 2;

    // hoisted xi-weights (constant across steps)
    float w0xi[6];
#pragma unroll
    for (int j = 0; j < 6; j++) w0xi[j] = W0[(size_t)(4096 + j) * HDn + tid];

    // register weight pipeline: preload chunk 0, k8=0
    uint2 br0[8], br1[8];
#pragma unroll
    for (int nf = 0; nf < 8; nf++) br0[nf] = *(const uint2*)(wbase + nf * 64);

    // X0 = exp_se3(0.1 * xi0)
    if (tid < 64) {
        float xi[6];
#pragma unroll
        for (int j = 0; j < 6; j++) xi[j] = 0.1f * xi0[(brow + tid) * 6 + j];
        exp_se3_dev(xi, &Xs[tid * 16]);
    }
    __syncthreads();

    for (int s = 0; s < ns; s++) {
        // phase 0: log_se3 of current state
        if (tid < 64) {
            float xi[6];
            log_se3_dev(&Xs[tid * 16], xi);
#pragma unroll
            for (int q = 0; q < 6; q++) xis[tid * 6 + q] = xi[q];
        }
        __syncthreads();

        // phase 1: input layer (column tid over 64 rows)
        {
            float tc;
            if (s < 32) tc = g_tembW[s * HDn + tid];
            else {
                tc = 0.0f;
                float tval = (float)s * dt;
#pragma unroll 8
                for (int d = 0; d < 64; d++) {
                    int j = d & 31;
                    float freq = expf(-(float)j * (logf(10000.0f) / 31.0f));
                    float e = tval * freq;
                    float tb = (d < 32) ? sinf(e) : cosf(e);
                    tc += tb * W0[(size_t)(4102 + d) * HDn + tid];
                }
            }
            for (int r = 0; r < 64; r++) {
                float v = g_H0[(size_t)(brow + r) * HDn + tid] + tc;
#pragma unroll
                for (int j = 0; j < 6; j++) v += xis[r * 6 + j] * w0xi[j];
                ys[r * YS + tid] = f2tf32(gelu_f(v));
            }
        }
        __syncthreads();
        block_ln32(ys, g0, be0, wid, lane);
        __syncthreads();

        // phase 2: 3 hidden layers, 48 chunks, register-pipelined LDG weights,
        // no block barriers inside a layer
        float acc[2][8][4];
        for (int gc = 0; gc < 48; gc++) {
            int ch = gc & 15, l = gc >> 4;
            if (ch == 0) {
#pragma unroll
                for (int mf = 0; mf < 2; mf++)
#pragma unroll
                    for (int nf = 0; nf < 8; nf++)
#pragma unroll
                        for (int q = 0; q < 4; q++) acc[mf][nf][q] = 0.0f;
            }
            const uint32_t* wb = wbase + (size_t)gc * 4096;
            // prefetch k8=1 of this chunk
#pragma unroll
            for (int nf = 0; nf < 8; nf++) br1[nf] = *(const uint2*)(wb + 2048 + nf * 64);
            // k8 = 0 MMAs (br0 preloaded)
            {
                int kcol = ch * 16;
                uint32_t a[2][4];
#pragma unroll
                for (int mf = 0; mf < 2; mf++) {
                    int r0 = warp_m + mf * 16 + g;
                    a[mf][0] = ys[r0 * YS + kcol + t];
                    a[mf][1] = ys[(r0 + 8) * YS + kcol + t];
                    a[mf][2] = ys[r0 * YS + kcol + t + 4];
                    a[mf][3] = ys[(r0 + 8) * YS + kcol + t + 4];
                }
#pragma unroll
                for (int nf = 0; nf < 8; nf++) {
                    mma_tf32(acc[0][nf], a[0][0], a[0][1], a[0][2], a[0][3], br0[nf].x, br0[nf].y);
                    mma_tf32(acc[1][nf], a[1][0], a[1][1], a[1][2], a[1][3], br0[nf].x, br0[nf].y);
                }
            }
            // prefetch k8=0 of next chunk (wraps to chunk 0 for next step)
            {
                int gn = (gc + 1 < 48) ? gc + 1 : 0;
                const uint32_t* wn_ = wbase + (size_t)gn * 4096;
#pragma unroll
                for (int nf = 0; nf < 8; nf++) br0[nf] = *(const uint2*)(wn_ + nf * 64);
            }
            // k8 = 1 MMAs
            {
                int kcol = ch * 16 + 8;
                uint32_t a[2][4];
#pragma unroll
                for (int mf = 0; mf < 2; mf++) {
                    int r0 = warp_m + mf * 16 + g;
                    a[mf][0] = ys[r0 * YS + kcol + t];
                    a[mf][1] = ys[(r0 + 8) * YS + kcol + t];
                    a[mf][2] = ys[r0 * YS + kcol + t + 4];
                    a[mf][3] = ys[(r0 + 8) * YS + kcol + t + 4];
                }
#pragma unroll
                for (int nf = 0; nf < 8; nf++) {
                    mma_tf32(acc[0][nf], a[0][0], a[0][1], a[0][2], a[0][3], br1[nf].x, br1[nf].y);
                    mma_tf32(acc[1][nf], a[1][0], a[1][1], a[1][2], a[1][3], br1[nf].x, br1[nf].y);
                }
            }
            if (ch == 15) {
                __syncthreads();   // all warps done reading ys for this layer
#pragma unroll
                for (int nf = 0; nf < 8; nf++) {
                    int c0 = warp_n + nf * 8 + 2 * t;
                    float bb0 = br[l * HDn + c0], bb1 = br[l * HDn + c0 + 1];
#pragma unroll
                    for (int mf = 0; mf < 2; mf++) {
                        int r0 = warp_m + mf * 16 + g;
                        ys[r0 * YS + c0]           = f2tf32(gelu_f(acc[mf][nf][0] + bb0));
                        ys[r0 * YS + c0 + 1]       = f2tf32(gelu_f(acc[mf][nf][1] + bb1));
                        ys[(r0 + 8) * YS + c0]     = f2tf32(gelu_f(acc[mf][nf][2] + bb0));
                        ys[(r0 + 8) * YS + c0 + 1] = f2tf32(gelu_f(acc[mf][nf][3] + bb1));
                    }
                }
                __syncthreads();
                block_ln32(ys, gr + l * HDn, ber + l * HDn, wid, lane);
                __syncthreads();
            }
        }

        // phase 3: v = y @ Wout + bout ; X = X @ exp_se3(dt*v)
        for (int rr = 0; rr < 8; rr++) {
            int r = wid * 8 + rr;
            float p[6] = {0, 0, 0, 0, 0, 0};
            for (int c = lane; c < HDn; c += 32) {
                float yv = __uint_as_float(ys[r * YS + c]);
                const float* wp = Wout + c * 6;
#pragma unroll
                for (int j = 0; j < 6; j++) p[j] += yv * wp[j];
            }
#pragma unroll
            for (int j = 0; j < 6; j++)
#pragma unroll
                for (int o = 16; o > 0; o >>= 1)
                    p[j] += __shfl_xor_sync(0xffffffffu, p[j], o);
            if (lane == 0) {
                float xi[6];
#pragma unroll
                for (int j = 0; j < 6; j++) xi[j] = dt * (p[j] + bout[j]);
                float M[16];
                exp_se3_dev(xi, M);
                float Xo[16];
#pragma unroll
                for (int q = 0; q < 16; q++) Xo[q] = Xs[r * 16 + q];
#pragma unroll
                for (int i = 0; i < 4; i++)
#pragma unroll
                    for (int j = 0; j < 4; j++) {
                        float sm = 0.0f;
#pragma unroll
                        for (int k = 0; k < 4; k++) sm += Xo[i * 4 + k] * M[k * 4 + j];
                        Xs[r * 16 + i * 4 + j] = sm;
                    }
            }
        }
        __syncthreads();   // Xs/ys stable for next step
    }

    // write final X to output
    {
        int row = tid >> 2, q4 = (tid & 3) * 4;
        float4 v = *(float4*)&Xs[row * 16 + q4];
        *(float4*)&out[(size_t)(brow + row) * 16 + q4] = v;
    }
}

// ---------------- launch ----------------
extern "C" void kernel_launch(void* const* d_in, const int* in_sizes, int n_in,
                              void* d_out, int out_size) {
    const float* h    = (const float*)d_in[0];
    const float* xi0  = (const float*)d_in[1];
    const float* W0   = (const float*)d_in[2];
    const float* b0   = (const float*)d_in[3];
    const float* g0   = (const float*)d_in[4];
    const float* be0  = (const float*)d_in[5];
    const float* Wr   = (const float*)d_in[6];
    const float* br   = (const float*)d_in[7];
    const float* gr   = (const float*)d_in[8];
    const float* ber  = (const float*)d_in[9];
    const float* Wout = (const float*)d_in[10];
    const float* bout = (const float*)d_in[11];
    const float* gW1  = (const float*)d_in[12];
    const float* gb1  = (const float*)d_in[13];
    const float* gW2  = (const float*)d_in[14];
    const float* gb2  = (const float*)d_in[15];
    const int*   nst  = (const int*)d_in[16];
    float* out = (float*)d_out;

    const int FUSED_SMEM = (4 + 2 * 128 * AP + 2 * 10240 + 128 * 4) * 4;   // ~121 KB
    const int ODE_SMEM   = (64 * YS + 64 * 16 + 64 * 6) * 4;               // ~71 KB
    cudaFuncSetAttribute(fused_h_kernel, cudaFuncAttributeMaxDynamicSharedMemorySize, FUSED_SMEM);
    cudaFuncSetAttribute(ode_kernel, cudaFuncAttributeMaxDynamicSharedMemorySize, ODE_SMEM);

    prep_wr32<<<384, 256>>>(Wr);
    prep_wc<<<2560, 256>>>(W0, gW1);
    prep_temb<<<32, 256>>>(W0, nst);
    fused_h_kernel<<<Bn / 128, 512, FUSED_SMEM>>>(h, b0, gb1, gW2, gb2, out);
    ode_kernel<<<Bn / 64, 256, ODE_SMEM>>>(xi0, W0, g0, be0, br, gr, ber,
                                           Wout, bout, nst, out);
}